// round 1
// baseline (speedup 1.0000x reference)
#include <cuda_runtime.h>

#define N_NODE 2048
#define DIM 256
#define D_SEQ 1280
#define HDH 384
#define N_HEAD 8
#define D_HEAD 48
#define B_GRAPH 8
#define S_LEN 1024
#define INV_SCALE 0.14433756729740643f  /* 1/sqrt(48) */

// ---------------- scratch (device globals; no allocs allowed) ----------------
__device__ float g_k[B_GRAPH * S_LEN * HDH];    // [b,s,h,d]
__device__ float g_v[B_GRAPH * S_LEN * HDH];
__device__ float g_q[N_NODE * HDH];
__device__ float g_gpre[N_NODE * HDH];
__device__ float g_feat[N_NODE * HDH];
__device__ int   g_numTiles;
__device__ int   g_tile_b[80];
__device__ int   g_tile_n0[80];
__device__ int   g_tile_nv[80];

// ---------------- kernel 0: segment batch, build node tiles ------------------
__global__ void setup_kernel(const void* batch_raw) {
    __shared__ int cnt[8];
    __shared__ int ok32;
    int tid = threadIdx.x;
    if (tid < 8) cnt[tid] = 0;
    if (tid == 0) ok32 = 1;
    __syncthreads();

    // Detect dtype: int32 view of an int64 buffer is [v,0,v,0,...] which is
    // non-sorted unless all-zero (then both views agree). Reading 2048 int32
    // = 8KB is safe for either dtype.
    const int* b32 = (const int*)batch_raw;
    int bad = 0;
    for (int i = tid; i < N_NODE; i += blockDim.x) {
        int v = b32[i];
        if (v < 0 || v >= 8) bad = 1;
        if (i + 1 < N_NODE && b32[i + 1] < v) bad = 1;
    }
    if (bad) ok32 = 0;
    __syncthreads();

    const long long* b64 = (const long long*)batch_raw;
    for (int i = tid; i < N_NODE; i += blockDim.x) {
        int v = ok32 ? b32[i] : (int)b64[i];
        v = min(max(v, 0), 7);
        atomicAdd(&cnt[v], 1);
    }
    __syncthreads();

    if (tid == 0) {
        int off = 0, t = 0;
        for (int b = 0; b < 8; b++) {
            int nb = cnt[b];
            for (int s = 0; s < nb; s += 32) {
                g_tile_b[t] = b;
                g_tile_n0[t] = off + s;
                g_tile_nv[t] = min(32, nb - s);
                t++;
            }
            off += nb;
        }
        g_numTiles = t;
    }
}

// ---------------- kernel 1: layernorm + Q + gate-preact ----------------------
// 8 nodes per block, 384 threads. Warp w<8 does LN for node w; then all 384
// threads each own one output column across the 8 nodes.
__global__ void __launch_bounds__(384) lnqg_kernel(
    const float* __restrict__ node,
    const float* __restrict__ ln_g, const float* __restrict__ ln_b,
    const float* __restrict__ Wq, const float* __restrict__ Wg,
    const float* __restrict__ bg)
{
    __shared__ float sy[8][DIM];
    int n0 = blockIdx.x * 8;
    int tid = threadIdx.x;
    int w = tid >> 5, lane = tid & 31;

    if (w < 8) {
        int n = n0 + w;
        float xv[8];
        float sx = 0.f, sxx = 0.f;
#pragma unroll
        for (int i = 0; i < 8; i++) {
            float x = node[n * DIM + lane + i * 32];
            xv[i] = x; sx += x; sxx += x * x;
        }
#pragma unroll
        for (int o = 16; o > 0; o >>= 1) {
            sx  += __shfl_xor_sync(0xffffffffu, sx, o);
            sxx += __shfl_xor_sync(0xffffffffu, sxx, o);
        }
        float mu = sx * (1.f / DIM);
        float var = sxx * (1.f / DIM) - mu * mu;
        float inv = rsqrtf(var + 1e-5f);
#pragma unroll
        for (int i = 0; i < 8; i++) {
            int d = lane + i * 32;
            sy[w][d] = (xv[i] - mu) * inv * ln_g[d] + ln_b[d];
        }
    }
    __syncthreads();

    int col = tid;  // 0..383
    float aq[8], ag[8];
#pragma unroll
    for (int j = 0; j < 8; j++) { aq[j] = 0.f; ag[j] = 0.f; }
    for (int d = 0; d < DIM; d++) {
        float wq = Wq[d * HDH + col];
        float wg = Wg[d * HDH + col];
#pragma unroll
        for (int j = 0; j < 8; j++) {
            float y = sy[j][d];
            aq[j] = fmaf(y, wq, aq[j]);
            ag[j] = fmaf(y, wg, ag[j]);
        }
    }
    float bgv = bg[col];
#pragma unroll
    for (int j = 0; j < 8; j++) {
        g_q[(n0 + j) * HDH + col] = aq[j];
        g_gpre[(n0 + j) * HDH + col] = ag[j] + bgv;
    }
}

// ---------------- kernel 2: K/V projection GEMM ------------------------------
// C[8192,768] = emb[8192,1280] @ [Wk|Wv]. 64x64x16 tiles, 4x4 per thread.
__global__ void __launch_bounds__(256) kv_gemm_kernel(
    const float* __restrict__ emb,
    const float* __restrict__ Wk, const float* __restrict__ Wv)
{
    __shared__ float As[16][64];
    __shared__ float Bs[16][64];

    int bn = blockIdx.x;   // 0..11 (0..5 -> K, 6..11 -> V)
    int bm = blockIdx.y;   // 0..127
    int tid = threadIdx.x;

    const float* W = (bn < 6) ? Wk : Wv;
    float* dst = (bn < 6) ? g_k : g_v;
    int n0 = (bn % 6) * 64;
    int m0 = bm * 64;

    int arow = tid >> 2, akq = (tid & 3) * 4;
    int brow = tid >> 4, bcol = (tid & 15) * 4;
    int ty = tid >> 4, tx = tid & 15;

    float c[4][4];
#pragma unroll
    for (int i = 0; i < 4; i++)
#pragma unroll
        for (int j = 0; j < 4; j++) c[i][j] = 0.f;

    for (int k0 = 0; k0 < D_SEQ; k0 += 16) {
        float4 a4 = *(const float4*)&emb[(m0 + arow) * D_SEQ + k0 + akq];
        As[akq + 0][arow] = a4.x;
        As[akq + 1][arow] = a4.y;
        As[akq + 2][arow] = a4.z;
        As[akq + 3][arow] = a4.w;
        *(float4*)&Bs[brow][bcol] = *(const float4*)&W[(k0 + brow) * HDH + n0 + bcol];
        __syncthreads();
#pragma unroll
        for (int kk = 0; kk < 16; kk++) {
            float4 a = *(const float4*)&As[kk][ty * 4];
            float4 b = *(const float4*)&Bs[kk][tx * 4];
            float ar[4] = {a.x, a.y, a.z, a.w};
            float br[4] = {b.x, b.y, b.z, b.w};
#pragma unroll
            for (int i = 0; i < 4; i++)
#pragma unroll
                for (int j = 0; j < 4; j++)
                    c[i][j] = fmaf(ar[i], br[j], c[i][j]);
        }
        __syncthreads();
    }
#pragma unroll
    for (int i = 0; i < 4; i++) {
        float4 o = make_float4(c[i][0], c[i][1], c[i][2], c[i][3]);
        *(float4*)&dst[(m0 + ty * 4 + i) * HDH + n0 + tx * 4] = o;
    }
}

// ---------------- kernel 3: attention (flash-style) --------------------------
// Block = (32-node batch-uniform tile) x (head pair). 8 warps:
// warp w -> head (w&1), s-stripe (w>>2... actually w>>1 in {0..3}).
// Lane j owns node j: q[48] and acc[48] in registers; K/V chunks in SMEM.
__global__ void __launch_bounds__(256) attn_kernel(const int* __restrict__ mask)
{
    extern __shared__ float sm[];
    float* sK   = sm;                 // [64][96]  (6144 floats)
    float* sV   = sm + 6144;          // [64][96]
    int*   sMask = (int*)(sm + 12288);  // [64]
    float* sML  = sm + 12352;         // [((st*32+j)*2+hl)][{m,l}]  (512 floats)
    float* cAcc = sm;                 // alias of sK+sV: [(st*32+j)*2+hl][48]

    int t = blockIdx.x >> 2;
    if (t >= g_numTiles) return;
    int hp = blockIdx.x & 3;
    int b = g_tile_b[t], n0 = g_tile_n0[t], nv = g_tile_nv[t];
    int tid = threadIdx.x, w = tid >> 5, lane = tid & 31;
    int hl = w & 1, st = w >> 1;
    int h = hp * 2 + hl;

    float qv[48];
    if (lane < nv) {
        const float4* qp = (const float4*)&g_q[(n0 + lane) * HDH + h * D_HEAD];
#pragma unroll
        for (int i = 0; i < 12; i++) {
            float4 v = qp[i];
            qv[4 * i] = v.x; qv[4 * i + 1] = v.y; qv[4 * i + 2] = v.z; qv[4 * i + 3] = v.w;
        }
    } else {
#pragma unroll
        for (int i = 0; i < 48; i++) qv[i] = 0.f;
    }

    float m = -1e30f, l = 0.f;
    float acc[48];
#pragma unroll
    for (int i = 0; i < 48; i++) acc[i] = 0.f;

    const float4* Kg = (const float4*)g_k;
    const float4* Vg = (const float4*)g_v;

    for (int c = 0; c < S_LEN; c += 64) {
        __syncthreads();
        int base = b * S_LEN + c;
#pragma unroll
        for (int q8 = 0; q8 < 6; q8++) {
            int idx = tid + q8 * 256;      // 0..1535 float4s
            int row = idx / 24, c4 = idx % 24;
            int gi = (base + row) * 96 + hp * 24 + c4;
            ((float4*)sK)[row * 24 + c4] = Kg[gi];
            ((float4*)sV)[row * 24 + c4] = Vg[gi];
        }
        if (tid < 64) sMask[tid] = mask[b * S_LEN + c + tid];
        __syncthreads();

        float sc16[16];
#pragma unroll 4
        for (int i = 0; i < 16; i++) {
            int s = 4 * i + st;
            if (sMask[s]) {
                const float* kr = &sK[s * 96 + hl * 48];
                float d0 = 0.f;
#pragma unroll
                for (int d = 0; d < 48; d++) d0 = fmaf(qv[d], kr[d], d0);
                sc16[i] = d0 * INV_SCALE;
            } else {
                sc16[i] = -1e30f;
            }
        }
        float mc = -1e30f;
#pragma unroll
        for (int i = 0; i < 16; i++) mc = fmaxf(mc, sc16[i]);
        if (mc > -1e29f) {
            float mn = fmaxf(m, mc);
            float f = __expf(m - mn);      // m==-1e30 -> 0
            l *= f;
#pragma unroll
            for (int d = 0; d < 48; d++) acc[d] *= f;
            m = mn;
#pragma unroll 2
            for (int i = 0; i < 16; i++) {
                if (sc16[i] > -1e29f) {
                    float p = __expf(sc16[i] - m);
                    l += p;
                    const float* vr = &sV[(4 * i + st) * 96 + hl * 48];
#pragma unroll
                    for (int d = 0; d < 48; d++) acc[d] = fmaf(p, vr[d], acc[d]);
                }
            }
        }
    }
    __syncthreads();

    // publish per-stripe partials
    {
        int r = (st * 32 + lane) * 2 + hl;
        sML[r * 2 + 0] = m;
        sML[r * 2 + 1] = l;
#pragma unroll
        for (int d = 0; d < 48; d++) cAcc[r * 48 + d] = acc[d];
    }
    __syncthreads();

    // merge 4 stripes per (node, head)
    if (tid < 64) {
        int j = tid >> 1, hlf = tid & 1;
        int hf = hp * 2 + hlf;
        float M = -1e30f;
#pragma unroll
        for (int s = 0; s < 4; s++)
            M = fmaxf(M, sML[((s * 32 + j) * 2 + hlf) * 2]);
        float L = 0.f, e[4];
#pragma unroll
        for (int s = 0; s < 4; s++) {
            float ms = sML[((s * 32 + j) * 2 + hlf) * 2];
            float ls = sML[((s * 32 + j) * 2 + hlf) * 2 + 1];
            e[s] = __expf(ms - M);
            L += ls * e[s];
        }
        float invL = 1.f / (L + 1e-9f);
        if (j < nv) {
            float* outp = &g_feat[(n0 + j) * HDH + hf * D_HEAD];
            for (int d = 0; d < 48; d++) {
                float F = 0.f;
#pragma unroll
                for (int s = 0; s < 4; s++)
                    F += cAcc[((s * 32 + j) * 2 + hlf) * 48 + d] * e[s];
                outp[d] = F * invL;
            }
        }
    }
}

// ---------------- kernel 4: gate * feat @ Wback + residual -------------------
__global__ void __launch_bounds__(256) out_kernel(
    const float* __restrict__ node, const float* __restrict__ Wback,
    const float* __restrict__ bback, float* __restrict__ out)
{
    __shared__ float sx[8][HDH];
    int n0 = blockIdx.x * 8;
    int tid = threadIdx.x;
    for (int idx = tid; idx < 8 * HDH; idx += 256) {
        int j = idx / HDH, cc = idx % HDH;
        float gpre = g_gpre[(n0 + j) * HDH + cc];
        float gate = 1.f / (1.f + __expf(-gpre));
        sx[j][cc] = gate * g_feat[(n0 + j) * HDH + cc];
    }
    __syncthreads();

    int col = tid;  // 0..255
    float a[8];
#pragma unroll
    for (int j = 0; j < 8; j++) a[j] = 0.f;
    for (int cc = 0; cc < HDH; cc++) {
        float wb = Wback[cc * DIM + col];
#pragma unroll
        for (int j = 0; j < 8; j++) a[j] = fmaf(sx[j][cc], wb, a[j]);
    }
    float bb = bback[col];
#pragma unroll
    for (int j = 0; j < 8; j++)
        out[(n0 + j) * DIM + col] = node[(n0 + j) * DIM + col] + a[j] + bb;
}

// ---------------- launch -----------------------------------------------------
extern "C" void kernel_launch(void* const* d_in, const int* in_sizes, int n_in,
                              void* d_out, int out_size) {
    const float* node  = (const float*)d_in[0];
    const float* emb   = (const float*)d_in[1];
    const int*   mask  = (const int*)d_in[2];
    const void*  batch = d_in[3];
    const float* ln_g  = (const float*)d_in[4];
    const float* ln_b  = (const float*)d_in[5];
    const float* Wq    = (const float*)d_in[6];
    const float* Wk    = (const float*)d_in[7];
    const float* Wv    = (const float*)d_in[8];
    const float* Wg    = (const float*)d_in[9];
    const float* bg    = (const float*)d_in[10];
    const float* Wback = (const float*)d_in[11];
    const float* bback = (const float*)d_in[12];
    float* out = (float*)d_out;

    cudaFuncSetAttribute(attn_kernel,
                         cudaFuncAttributeMaxDynamicSharedMemorySize, 64 * 1024);

    setup_kernel<<<1, 256>>>(batch);
    lnqg_kernel<<<N_NODE / 8, 384>>>(node, ln_g, ln_b, Wq, Wg, bg);
    kv_gemm_kernel<<<dim3(12, 128), 256>>>(emb, Wk, Wv);
    attn_kernel<<<288, 256, 12864 * sizeof(float)>>>(mask);
    out_kernel<<<N_NODE / 8, 256>>>(node, Wback, bback, out);
}

// round 9
// speedup vs baseline: 1.5750x; 1.5750x over previous
#include <cuda_runtime.h>
#include <cstdint>

#define N_NODE 2048
#define DIM 256
#define D_SEQ 1280
#define HDH 384
#define N_HEAD 8
#define D_HEAD 48
#define B_GRAPH 8
#define S_LEN 1024
#define INV_SCALE 0.14433756729740643f  /* 1/sqrt(48) */

// ---------------- scratch (device globals; no allocs allowed) ----------------
__device__ float g_k[B_GRAPH * S_LEN * HDH];    // [b,s,h,d]
__device__ float g_v[B_GRAPH * S_LEN * HDH];
__device__ float g_q[N_NODE * HDH];
__device__ float g_gpre[N_NODE * HDH];
__device__ float g_feat[N_NODE * HDH];
__device__ float g_wt[768 * D_SEQ];             // [n,k] transposed [Wk|Wv]
__device__ int   g_numTiles;
__device__ int   g_tile_b[80];
__device__ int   g_tile_n0[80];
__device__ int   g_tile_nv[80];

// ---------------- kernel 0: segment batch, build node tiles ------------------
__global__ void setup_kernel(const void* batch_raw) {
    __shared__ int cnt[8];
    __shared__ int ok32;
    int tid = threadIdx.x;
    if (tid < 8) cnt[tid] = 0;
    if (tid == 0) ok32 = 1;
    __syncthreads();
    const int* b32 = (const int*)batch_raw;
    int bad = 0;
    for (int i = tid; i < N_NODE; i += blockDim.x) {
        int v = b32[i];
        if (v < 0 || v >= 8) bad = 1;
        if (i + 1 < N_NODE && b32[i + 1] < v) bad = 1;
    }
    if (bad) ok32 = 0;
    __syncthreads();
    const long long* b64 = (const long long*)batch_raw;
    for (int i = tid; i < N_NODE; i += blockDim.x) {
        int v = ok32 ? b32[i] : (int)b64[i];
        v = min(max(v, 0), 7);
        atomicAdd(&cnt[v], 1);
    }
    __syncthreads();
    if (tid == 0) {
        int off = 0, t = 0;
        for (int b = 0; b < 8; b++) {
            int nb = cnt[b];
            for (int s = 0; s < nb; s += 32) {
                g_tile_b[t] = b;
                g_tile_n0[t] = off + s;
                g_tile_nv[t] = min(32, nb - s);
                t++;
            }
            off += nb;
        }
        g_numTiles = t;
    }
}

// ---------------- kernel 0b: transpose [Wk|Wv] -> g_wt[n][k] -----------------
__global__ void __launch_bounds__(256) wt_kernel(const float* __restrict__ Wk,
                                                 const float* __restrict__ Wv) {
    __shared__ float tile[32][33];
    int kb = blockIdx.x * 32, nb = blockIdx.y * 32;
    int tx = threadIdx.x & 31, ty = threadIdx.x >> 5;  // 32 x 8
    const float* W = (nb < 384) ? Wk : Wv;
    int nf = (nb < 384) ? nb : nb - 384;
#pragma unroll
    for (int i = 0; i < 4; i++)
        tile[ty + i * 8][tx] = W[(kb + ty + i * 8) * HDH + nf + tx];
    __syncthreads();
#pragma unroll
    for (int i = 0; i < 4; i++)
        g_wt[(nb + ty + i * 8) * D_SEQ + kb + tx] = tile[tx][ty + i * 8];
}

// ---------------- kernel 1: layernorm + Q + gate-preact ----------------------
__global__ void __launch_bounds__(384) lnqg_kernel(
    const float* __restrict__ node,
    const float* __restrict__ ln_g, const float* __restrict__ ln_b,
    const float* __restrict__ Wq, const float* __restrict__ Wg,
    const float* __restrict__ bg)
{
    __shared__ float sy[8][DIM];
    int n0 = blockIdx.x * 8;
    int tid = threadIdx.x;
    int w = tid >> 5, lane = tid & 31;

    if (w < 8) {
        int n = n0 + w;
        float xv[8];
        float sx = 0.f, sxx = 0.f;
#pragma unroll
        for (int i = 0; i < 8; i++) {
            float x = node[n * DIM + lane + i * 32];
            xv[i] = x; sx += x; sxx += x * x;
        }
#pragma unroll
        for (int o = 16; o > 0; o >>= 1) {
            sx  += __shfl_xor_sync(0xffffffffu, sx, o);
            sxx += __shfl_xor_sync(0xffffffffu, sxx, o);
        }
        float mu = sx * (1.f / DIM);
        float var = sxx * (1.f / DIM) - mu * mu;
        float inv = rsqrtf(var + 1e-5f);
#pragma unroll
        for (int i = 0; i < 8; i++) {
            int d = lane + i * 32;
            sy[w][d] = (xv[i] - mu) * inv * ln_g[d] + ln_b[d];
        }
    }
    __syncthreads();

    int col = tid;
    float aq[8], ag[8];
#pragma unroll
    for (int j = 0; j < 8; j++) { aq[j] = 0.f; ag[j] = 0.f; }
    for (int d = 0; d < DIM; d++) {
        float wq = Wq[d * HDH + col];
        float wg = Wg[d * HDH + col];
#pragma unroll
        for (int j = 0; j < 8; j++) {
            float y = sy[j][d];
            aq[j] = fmaf(y, wq, aq[j]);
            ag[j] = fmaf(y, wg, ag[j]);
        }
    }
    float bgv = bg[col];
#pragma unroll
    for (int j = 0; j < 8; j++) {
        g_q[(n0 + j) * HDH + col] = aq[j];
        g_gpre[(n0 + j) * HDH + col] = ag[j] + bgv;
    }
}

// ---------------- kernel 2: K/V projection via mma.sync TF32 -----------------
// C[8192,768] = emb[8192,1280] @ W[1280,768];  B = g_wt[n][k] (K-major).
// CTA tile M=128 x N=64; 8 warps (4x2); warp tile 32x32 = 2x4 m16n8k8 tiles.
// Smem stride 36 floats: 16B-aligned STS.128 AND conflict-free fragment LDS
// (bank = (4r+c) mod 32 is a bijection over the warp's (r,c) pattern).
#define KV_STRIDE 36

__device__ __forceinline__ uint32_t to_tf32(float f) {
    uint32_t o;
    asm("cvt.rna.tf32.f32 %0, %1;" : "=r"(o) : "f"(f));
    return o;
}

#define MMA_TF32(c, a, b) \
    asm volatile("mma.sync.aligned.m16n8k8.row.col.f32.tf32.tf32.f32 " \
        "{%0,%1,%2,%3}, {%4,%5,%6,%7}, {%8,%9}, {%0,%1,%2,%3};" \
        : "+f"((c)[0]), "+f"((c)[1]), "+f"((c)[2]), "+f"((c)[3]) \
        : "r"((a)[0]), "r"((a)[1]), "r"((a)[2]), "r"((a)[3]), \
          "r"((b)[0]), "r"((b)[1]))

__global__ void __launch_bounds__(256) kv_mma_kernel(const float* __restrict__ emb)
{
    __shared__ uint32_t sA[128 * KV_STRIDE];
    __shared__ uint32_t sB[64 * KV_STRIDE];

    int tid = threadIdx.x;
    int wid = tid >> 5, lane = tid & 31;
    int warp_m = wid & 3, warp_n = wid >> 2;
    int lr = lane >> 2, lc = lane & 3;

    int m0 = (int)blockIdx.x * 128;   // 64
    int n0 = (int)blockIdx.y * 64;    // 12

    // global load slots
    int arow = tid >> 1, ahalf = tid & 1;                 // A: 4 float4 / thread
    const float* gA = emb + (size_t)(m0 + arow) * D_SEQ + ahalf * 16;
    int brow = tid >> 2, bq = tid & 3;                    // B: 2 float4 / thread
    const float* gB = g_wt + (size_t)(n0 + brow) * D_SEQ + bq * 8;

    float acc[2][4][4];
#pragma unroll
    for (int mt = 0; mt < 2; mt++)
#pragma unroll
        for (int nt = 0; nt < 4; nt++)
#pragma unroll
            for (int i = 0; i < 4; i++) acc[mt][nt][i] = 0.f;

    float4 rA[4], rB[2];
#pragma unroll
    for (int j = 0; j < 4; j++) rA[j] = *(const float4*)(gA + j * 4);
#pragma unroll
    for (int j = 0; j < 2; j++) rB[j] = *(const float4*)(gB + j * 4);

    for (int ch = 0; ch < 40; ch++) {
        __syncthreads();
#pragma unroll
        for (int j = 0; j < 4; j++) {
            uint4 u = make_uint4(to_tf32(rA[j].x), to_tf32(rA[j].y),
                                 to_tf32(rA[j].z), to_tf32(rA[j].w));
            *(uint4*)&sA[arow * KV_STRIDE + ahalf * 16 + j * 4] = u;
        }
#pragma unroll
        for (int j = 0; j < 2; j++) {
            uint4 u = make_uint4(to_tf32(rB[j].x), to_tf32(rB[j].y),
                                 to_tf32(rB[j].z), to_tf32(rB[j].w));
            *(uint4*)&sB[brow * KV_STRIDE + bq * 8 + j * 4] = u;
        }
        __syncthreads();
        if (ch < 39) {
            int k0 = (ch + 1) * 32;
#pragma unroll
            for (int j = 0; j < 4; j++) rA[j] = *(const float4*)(gA + k0 + j * 4);
#pragma unroll
            for (int j = 0; j < 2; j++) rB[j] = *(const float4*)(gB + k0 + j * 4);
        }
#pragma unroll
        for (int ks = 0; ks < 4; ks++) {
            int kk = ks * 8;
            uint32_t af[2][4];
#pragma unroll
            for (int mt = 0; mt < 2; mt++) {
                int r = warp_m * 32 + mt * 16 + lr;
                int c = kk + lc;
                af[mt][0] = sA[r * KV_STRIDE + c];
                af[mt][1] = sA[(r + 8) * KV_STRIDE + c];
                af[mt][2] = sA[r * KV_STRIDE + c + 4];
                af[mt][3] = sA[(r + 8) * KV_STRIDE + c + 4];
            }
            uint32_t bf[4][2];
#pragma unroll
            for (int nt = 0; nt < 4; nt++) {
                int n = warp_n * 32 + nt * 8 + lr;
                bf[nt][0] = sB[n * KV_STRIDE + kk + lc];
                bf[nt][1] = sB[n * KV_STRIDE + kk + lc + 4];
            }
#pragma unroll
            for (int mt = 0; mt < 2; mt++)
#pragma unroll
                for (int nt = 0; nt < 4; nt++)
                    MMA_TF32(acc[mt][nt], af[mt], bf[nt]);
        }
    }

    // epilogue: direct STG.64 (CTA's 64-col span never crosses the K/V split)
    float* dst;
    int nc0;
    if (n0 < 384) { dst = g_k; nc0 = n0; }
    else          { dst = g_v; nc0 = n0 - 384; }
#pragma unroll
    for (int mt = 0; mt < 2; mt++) {
        int r = m0 + warp_m * 32 + mt * 16 + lr;
#pragma unroll
        for (int nt = 0; nt < 4; nt++) {
            int c = nc0 + warp_n * 32 + nt * 8 + 2 * lc;
            *(float2*)&dst[(size_t)r * HDH + c] =
                make_float2(acc[mt][nt][0], acc[mt][nt][1]);
            *(float2*)&dst[(size_t)(r + 8) * HDH + c] =
                make_float2(acc[mt][nt][2], acc[mt][nt][3]);
        }
    }
}

// ---------------- kernel 3: attention (flash-style, float4 smem) -------------
__global__ void __launch_bounds__(256) attn_kernel(const int* __restrict__ mask)
{
    extern __shared__ float sm[];
    float* sK   = sm;                   // [64][96]
    float* sV   = sm + 6144;            // [64][96]
    int*   sMask = (int*)(sm + 12288);  // [64]
    float* sML  = sm + 12352;           // 512 floats
    float* cAcc = sm;                   // alias for partial accs

    int t = blockIdx.x >> 2;
    if (t >= g_numTiles) return;
    int hp = blockIdx.x & 3;
    int b = g_tile_b[t], n0 = g_tile_n0[t], nv = g_tile_nv[t];
    int tid = threadIdx.x, w = tid >> 5, lane = tid & 31;
    int hl = w & 1, st = w >> 1;
    int h = hp * 2 + hl;

    float qv[48];
    if (lane < nv) {
        const float4* qp = (const float4*)&g_q[(n0 + lane) * HDH + h * D_HEAD];
#pragma unroll
        for (int i = 0; i < 12; i++) {
            float4 v = qp[i];
            qv[4 * i] = v.x; qv[4 * i + 1] = v.y; qv[4 * i + 2] = v.z; qv[4 * i + 3] = v.w;
        }
    } else {
#pragma unroll
        for (int i = 0; i < 48; i++) qv[i] = 0.f;
    }

    float m = -1e30f, l = 0.f;
    float acc[48];
#pragma unroll
    for (int i = 0; i < 48; i++) acc[i] = 0.f;

    const float4* Kg = (const float4*)g_k;
    const float4* Vg = (const float4*)g_v;

    for (int c = 0; c < S_LEN; c += 64) {
        __syncthreads();
        int base = b * S_LEN + c;
#pragma unroll
        for (int q8 = 0; q8 < 6; q8++) {
            int idx = tid + q8 * 256;
            int row = idx / 24, c4 = idx % 24;
            int gi = (base + row) * 96 + hp * 24 + c4;
            ((float4*)sK)[row * 24 + c4] = Kg[gi];
            ((float4*)sV)[row * 24 + c4] = Vg[gi];
        }
        if (tid < 64) sMask[tid] = mask[b * S_LEN + c + tid];
        __syncthreads();

        float sc16[16];
#pragma unroll 4
        for (int i = 0; i < 16; i++) {
            int s = 4 * i + st;
            if (sMask[s]) {
                const float4* kr = (const float4*)&sK[s * 96 + hl * 48];
                float d0 = 0.f, d1 = 0.f, d2 = 0.f, d3 = 0.f;
#pragma unroll
                for (int i4 = 0; i4 < 12; i4++) {
                    float4 kk = kr[i4];
                    d0 = fmaf(qv[4 * i4 + 0], kk.x, d0);
                    d1 = fmaf(qv[4 * i4 + 1], kk.y, d1);
                    d2 = fmaf(qv[4 * i4 + 2], kk.z, d2);
                    d3 = fmaf(qv[4 * i4 + 3], kk.w, d3);
                }
                sc16[i] = ((d0 + d1) + (d2 + d3)) * INV_SCALE;
            } else {
                sc16[i] = -1e30f;
            }
        }
        float mc = -1e30f;
#pragma unroll
        for (int i = 0; i < 16; i++) mc = fmaxf(mc, sc16[i]);
        if (mc > -1e29f) {
            float mn = fmaxf(m, mc);
            float f = __expf(m - mn);
            l *= f;
#pragma unroll
            for (int d = 0; d < 48; d++) acc[d] *= f;
            m = mn;
#pragma unroll 2
            for (int i = 0; i < 16; i++) {
                if (sc16[i] > -1e29f) {
                    float p = __expf(sc16[i] - m);
                    l += p;
                    const float4* vr = (const float4*)&sV[(4 * i + st) * 96 + hl * 48];
#pragma unroll
                    for (int i4 = 0; i4 < 12; i4++) {
                        float4 vv = vr[i4];
                        acc[4 * i4 + 0] = fmaf(p, vv.x, acc[4 * i4 + 0]);
                        acc[4 * i4 + 1] = fmaf(p, vv.y, acc[4 * i4 + 1]);
                        acc[4 * i4 + 2] = fmaf(p, vv.z, acc[4 * i4 + 2]);
                        acc[4 * i4 + 3] = fmaf(p, vv.w, acc[4 * i4 + 3]);
                    }
                }
            }
        }
    }
    __syncthreads();

    {
        int r = (st * 32 + lane) * 2 + hl;
        sML[r * 2 + 0] = m;
        sML[r * 2 + 1] = l;
#pragma unroll
        for (int d = 0; d < 48; d++) cAcc[r * 48 + d] = acc[d];
    }
    __syncthreads();

    if (tid < 64) {
        int j = tid >> 1, hlf = tid & 1;
        int hf = hp * 2 + hlf;
        float M = -1e30f;
#pragma unroll
        for (int s = 0; s < 4; s++)
            M = fmaxf(M, sML[((s * 32 + j) * 2 + hlf) * 2]);
        float L = 0.f, e[4];
#pragma unroll
        for (int s = 0; s < 4; s++) {
            float ms = sML[((s * 32 + j) * 2 + hlf) * 2];
            float ls = sML[((s * 32 + j) * 2 + hlf) * 2 + 1];
            e[s] = __expf(ms - M);
            L += ls * e[s];
        }
        float invL = 1.f / (L + 1e-9f);
        if (j < nv) {
            float* outp = &g_feat[(n0 + j) * HDH + hf * D_HEAD];
            for (int d = 0; d < 48; d++) {
                float F = 0.f;
#pragma unroll
                for (int s = 0; s < 4; s++)
                    F += cAcc[((s * 32 + j) * 2 + hlf) * 48 + d] * e[s];
                outp[d] = F * invL;
            }
        }
    }
}

// ---------------- kernel 4: gate * feat @ Wback + residual -------------------
__global__ void __launch_bounds__(256) out_kernel(
    const float* __restrict__ node, const float* __restrict__ Wback,
    const float* __restrict__ bback, float* __restrict__ out)
{
    __shared__ float sx[8][HDH];
    int n0 = blockIdx.x * 8;
    int tid = threadIdx.x;
    for (int idx = tid; idx < 8 * HDH; idx += 256) {
        int j = idx / HDH, cc = idx % HDH;
        float gpre = g_gpre[(n0 + j) * HDH + cc];
        float gate = 1.f / (1.f + __expf(-gpre));
        sx[j][cc] = gate * g_feat[(n0 + j) * HDH + cc];
    }
    __syncthreads();

    int col = tid;
    float a[8];
#pragma unroll
    for (int j = 0; j < 8; j++) a[j] = 0.f;
    for (int cc = 0; cc < HDH; cc++) {
        float wb = Wback[cc * DIM + col];
#pragma unroll
        for (int j = 0; j < 8; j++) a[j] = fmaf(sx[j][cc], wb, a[j]);
    }
    float bb = bback[col];
#pragma unroll
    for (int j = 0; j < 8; j++)
        out[(n0 + j) * DIM + col] = node[(n0 + j) * DIM + col] + a[j] + bb;
}

// ---------------- launch -----------------------------------------------------
extern "C" void kernel_launch(void* const* d_in, const int* in_sizes, int n_in,
                              void* d_out, int out_size) {
    const float* node  = (const float*)d_in[0];
    const float* emb   = (const float*)d_in[1];
    const int*   mask  = (const int*)d_in[2];
    const void*  batch = d_in[3];
    const float* ln_g  = (const float*)d_in[4];
    const float* ln_b  = (const float*)d_in[5];
    const float* Wq    = (const float*)d_in[6];
    const float* Wk    = (const float*)d_in[7];
    const float* Wv    = (const float*)d_in[8];
    const float* Wg    = (const float*)d_in[9];
    const float* bg    = (const float*)d_in[10];
    const float* Wback = (const float*)d_in[11];
    const float* bback = (const float*)d_in[12];
    float* out = (float*)d_out;

    cudaFuncSetAttribute(attn_kernel,
                         cudaFuncAttributeMaxDynamicSharedMemorySize, 64 * 1024);

    setup_kernel<<<1, 256>>>(batch);
    wt_kernel<<<dim3(D_SEQ / 32, 768 / 32), 256>>>(Wk, Wv);
    lnqg_kernel<<<N_NODE / 8, 384>>>(node, ln_g, ln_b, Wq, Wg, bg);
    kv_mma_kernel<<<dim3(64, 12), 256>>>(emb);
    attn_kernel<<<288, 256, 12864 * sizeof(float)>>>(mask);
    out_kernel<<<N_NODE / 8, 256>>>(node, Wback, bback, out);
}

// round 10
// speedup vs baseline: 1.5921x; 1.0109x over previous
#include <cuda_runtime.h>
#include <cstdint>

#define N_NODE 2048
#define DIM 256
#define D_SEQ 1280
#define HDH 384
#define N_HEAD 8
#define D_HEAD 48
#define B_GRAPH 8
#define S_LEN 1024
#define INV_SCALE 0.14433756729740643f  /* 1/sqrt(48) */

// ---------------- scratch (device globals; no allocs allowed) ----------------
__device__ __align__(128) float g_k[B_GRAPH * S_LEN * HDH];    // [b,s,h,d]
__device__ __align__(128) float g_v[B_GRAPH * S_LEN * HDH];
__device__ __align__(128) float g_q[N_NODE * HDH];
__device__ __align__(128) float g_gpre[N_NODE * HDH];
__device__ __align__(128) float g_feat[N_NODE * HDH];
__device__ __align__(128) float g_wt[768 * D_SEQ];             // [n,k] tf32-rounded
__device__ __align__(128) float g_embt[8192 * D_SEQ];          // tf32-rounded emb
__device__ int   g_numTiles;
__device__ int   g_tile_b[80];
__device__ int   g_tile_n0[80];
__device__ int   g_tile_nv[80];

__device__ __forceinline__ uint32_t smem_u32(const void* p) {
    uint32_t a;
    asm("{ .reg .u64 t; cvta.to.shared.u64 t, %1; cvt.u32.u64 %0, t; }"
        : "=r"(a) : "l"(p));
    return a;
}
__device__ __forceinline__ uint32_t to_tf32(float f) {
    uint32_t o;
    asm("cvt.rna.tf32.f32 %0, %1;" : "=r"(o) : "f"(f));
    return o;
}
#define CP16(dst, src) \
    asm volatile("cp.async.cg.shared.global [%0], [%1], 16;" \
                 :: "r"(dst), "l"(src) : "memory")
#define CP_COMMIT() asm volatile("cp.async.commit_group;" ::: "memory")
#define CP_WAIT1()  asm volatile("cp.async.wait_group 1;" ::: "memory")
#define CP_WAIT0()  asm volatile("cp.async.wait_group 0;" ::: "memory")

// ---------------- kernel 0: segment batch, build node tiles ------------------
__global__ void setup_kernel(const void* batch_raw) {
    __shared__ int cnt[8];
    __shared__ int ok32;
    int tid = threadIdx.x;
    if (tid < 8) cnt[tid] = 0;
    if (tid == 0) ok32 = 1;
    __syncthreads();
    const int* b32 = (const int*)batch_raw;
    int bad = 0;
    for (int i = tid; i < N_NODE; i += blockDim.x) {
        int v = b32[i];
        if (v < 0 || v >= 8) bad = 1;
        if (i + 1 < N_NODE && b32[i + 1] < v) bad = 1;
    }
    if (bad) ok32 = 0;
    __syncthreads();
    const long long* b64 = (const long long*)batch_raw;
    for (int i = tid; i < N_NODE; i += blockDim.x) {
        int v = ok32 ? b32[i] : (int)b64[i];
        v = min(max(v, 0), 7);
        atomicAdd(&cnt[v], 1);
    }
    __syncthreads();
    if (tid == 0) {
        int off = 0, t = 0;
        for (int b = 0; b < 8; b++) {
            int nb = cnt[b];
            for (int s = 0; s < nb; s += 32) {
                g_tile_b[t] = b;
                g_tile_n0[t] = off + s;
                g_tile_nv[t] = min(32, nb - s);
                t++;
            }
            off += nb;
        }
        g_numTiles = t;
    }
}

// ---------------- kernel 0a: round emb to tf32 (rna) -> g_embt ---------------
__global__ void __launch_bounds__(256) cvt_kernel(const float* __restrict__ emb) {
    int i = blockIdx.x * 256 + threadIdx.x;   // float4 index; grid covers exactly
    float4 v = ((const float4*)emb)[i];
    float4 o;
    o.x = __uint_as_float(to_tf32(v.x));
    o.y = __uint_as_float(to_tf32(v.y));
    o.z = __uint_as_float(to_tf32(v.z));
    o.w = __uint_as_float(to_tf32(v.w));
    ((float4*)g_embt)[i] = o;
}

// ---------------- kernel 0b: transpose+round [Wk|Wv] -> g_wt[n][k] -----------
__global__ void __launch_bounds__(256) wt_kernel(const float* __restrict__ Wk,
                                                 const float* __restrict__ Wv) {
    __shared__ float tile[32][33];
    int kb = blockIdx.x * 32, nb = blockIdx.y * 32;
    int tx = threadIdx.x & 31, ty = threadIdx.x >> 5;  // 32 x 8
    const float* W = (nb < 384) ? Wk : Wv;
    int nf = (nb < 384) ? nb : nb - 384;
#pragma unroll
    for (int i = 0; i < 4; i++)
        tile[ty + i * 8][tx] = W[(kb + ty + i * 8) * HDH + nf + tx];
    __syncthreads();
#pragma unroll
    for (int i = 0; i < 4; i++)
        g_wt[(nb + ty + i * 8) * D_SEQ + kb + tx] =
            __uint_as_float(to_tf32(tile[tx][ty + i * 8]));
}

// ---------------- kernel 1: layernorm + Q + gate-preact ----------------------
__global__ void __launch_bounds__(384) lnqg_kernel(
    const float* __restrict__ node,
    const float* __restrict__ ln_g, const float* __restrict__ ln_b,
    const float* __restrict__ Wq, const float* __restrict__ Wg,
    const float* __restrict__ bg)
{
    __shared__ float sy[8][DIM];
    int n0 = blockIdx.x * 8;
    int tid = threadIdx.x;
    int w = tid >> 5, lane = tid & 31;

    if (w < 8) {
        int n = n0 + w;
        float xv[8];
        float sx = 0.f, sxx = 0.f;
#pragma unroll
        for (int i = 0; i < 8; i++) {
            float x = node[n * DIM + lane + i * 32];
            xv[i] = x; sx += x; sxx += x * x;
        }
#pragma unroll
        for (int o = 16; o > 0; o >>= 1) {
            sx  += __shfl_xor_sync(0xffffffffu, sx, o);
            sxx += __shfl_xor_sync(0xffffffffu, sxx, o);
        }
        float mu = sx * (1.f / DIM);
        float var = sxx * (1.f / DIM) - mu * mu;
        float inv = rsqrtf(var + 1e-5f);
#pragma unroll
        for (int i = 0; i < 8; i++) {
            int d = lane + i * 32;
            sy[w][d] = (xv[i] - mu) * inv * ln_g[d] + ln_b[d];
        }
    }
    __syncthreads();

    int col = tid;
    float aq[8], ag[8];
#pragma unroll
    for (int j = 0; j < 8; j++) { aq[j] = 0.f; ag[j] = 0.f; }
    for (int d = 0; d < DIM; d++) {
        float wq = Wq[d * HDH + col];
        float wg = Wg[d * HDH + col];
#pragma unroll
        for (int j = 0; j < 8; j++) {
            float y = sy[j][d];
            aq[j] = fmaf(y, wq, aq[j]);
            ag[j] = fmaf(y, wg, ag[j]);
        }
    }
    float bgv = bg[col];
#pragma unroll
    for (int j = 0; j < 8; j++) {
        g_q[(n0 + j) * HDH + col] = aq[j];
        g_gpre[(n0 + j) * HDH + col] = ag[j] + bgv;
    }
}

// ---------------- kernel 2: K/V projection, TF32 mma.sync + cp.async ---------
// C[8192,768] = g_embt @ g_wt^T.  CTA 128x64, warp 32x32, 2-stage cp.async.
#define KV_STRIDE 36
#define KV_STAGE_U32 ((128 + 64) * KV_STRIDE)   // 6912 u32 = 27648 B
#define KV_SMEM_BYTES (2 * KV_STAGE_U32 * 4)    // 55296 B

#define MMA_TF32(c, a, b) \
    asm volatile("mma.sync.aligned.m16n8k8.row.col.f32.tf32.tf32.f32 " \
        "{%0,%1,%2,%3}, {%4,%5,%6,%7}, {%8,%9}, {%0,%1,%2,%3};" \
        : "+f"((c)[0]), "+f"((c)[1]), "+f"((c)[2]), "+f"((c)[3]) \
        : "r"((a)[0]), "r"((a)[1]), "r"((a)[2]), "r"((a)[3]), \
          "r"((b)[0]), "r"((b)[1]))

__global__ void __launch_bounds__(256, 4) kv_mma_kernel()
{
    extern __shared__ uint32_t skv[];
    uint32_t sb = smem_u32(skv);

    int tid = threadIdx.x;
    int wid = tid >> 5, lane = tid & 31;
    int warp_m = wid & 3, warp_n = wid >> 2;
    int lr = lane >> 2, lc = lane & 3;

    int m0 = (int)blockIdx.x * 128;   // 64
    int n0 = (int)blockIdx.y * 64;    // 12

    int arow = tid >> 1, ahalf = tid & 1;                 // A: 4 cp16 / thread
    const char* gA = (const char*)(g_embt + (size_t)(m0 + arow) * D_SEQ + ahalf * 16);
    int brow = tid >> 2, bq = tid & 3;                    // B: 2 cp16 / thread
    const char* gB = (const char*)(g_wt + (size_t)(n0 + brow) * D_SEQ + bq * 8);
    uint32_t dA = sb + (uint32_t)(arow * KV_STRIDE + ahalf * 16) * 4;
    uint32_t dB = sb + (uint32_t)(128 * KV_STRIDE + brow * KV_STRIDE + bq * 8) * 4;

    float acc[2][4][4];
#pragma unroll
    for (int mt = 0; mt < 2; mt++)
#pragma unroll
        for (int nt = 0; nt < 4; nt++)
#pragma unroll
            for (int i = 0; i < 4; i++) acc[mt][nt][i] = 0.f;

    // prologue: chunks 0,1
#pragma unroll
    for (int st = 0; st < 2; st++) {
        uint32_t off = st * (KV_STAGE_U32 * 4);
        int kb = st * 32 * 4;  // bytes
#pragma unroll
        for (int j = 0; j < 4; j++) CP16(dA + off + j * 16, gA + kb + j * 16);
#pragma unroll
        for (int j = 0; j < 2; j++) CP16(dB + off + j * 16, gB + kb + j * 16);
        CP_COMMIT();
    }

    for (int ch = 0; ch < 40; ch++) {
        CP_WAIT1();
        __syncthreads();
        const uint32_t* sA = skv + (ch & 1) * KV_STAGE_U32;
        const uint32_t* sBp = sA + 128 * KV_STRIDE;

#pragma unroll
        for (int ks = 0; ks < 4; ks++) {
            int kk = ks * 8;
            uint32_t af[2][4];
#pragma unroll
            for (int mt = 0; mt < 2; mt++) {
                int r = warp_m * 32 + mt * 16 + lr;
                int c = kk + lc;
                af[mt][0] = sA[r * KV_STRIDE + c];
                af[mt][1] = sA[(r + 8) * KV_STRIDE + c];
                af[mt][2] = sA[r * KV_STRIDE + c + 4];
                af[mt][3] = sA[(r + 8) * KV_STRIDE + c + 4];
            }
            uint32_t bf[4][2];
#pragma unroll
            for (int nt = 0; nt < 4; nt++) {
                int n = warp_n * 32 + nt * 8 + lr;
                bf[nt][0] = sBp[n * KV_STRIDE + kk + lc];
                bf[nt][1] = sBp[n * KV_STRIDE + kk + lc + 4];
            }
#pragma unroll
            for (int mt = 0; mt < 2; mt++)
#pragma unroll
                for (int nt = 0; nt < 4; nt++)
                    MMA_TF32(acc[mt][nt], af[mt], bf[nt]);
        }
        __syncthreads();
        if (ch < 38) {
            uint32_t off = (ch & 1) * (KV_STAGE_U32 * 4);
            int kb = (ch + 2) * 32 * 4;  // bytes
#pragma unroll
            for (int j = 0; j < 4; j++) CP16(dA + off + j * 16, gA + kb + j * 16);
#pragma unroll
            for (int j = 0; j < 2; j++) CP16(dB + off + j * 16, gB + kb + j * 16);
        }
        CP_COMMIT();
    }

    // epilogue: direct STG.64 (CTA's 64-col span never crosses the K/V split)
    float* dst;
    int nc0;
    if (n0 < 384) { dst = g_k; nc0 = n0; }
    else          { dst = g_v; nc0 = n0 - 384; }
#pragma unroll
    for (int mt = 0; mt < 2; mt++) {
        int r = m0 + warp_m * 32 + mt * 16 + lr;
#pragma unroll
        for (int nt = 0; nt < 4; nt++) {
            int c = nc0 + warp_n * 32 + nt * 8 + 2 * lc;
            *(float2*)&dst[(size_t)r * HDH + c] =
                make_float2(acc[mt][nt][0], acc[mt][nt][1]);
            *(float2*)&dst[(size_t)(r + 8) * HDH + c] =
                make_float2(acc[mt][nt][2], acc[mt][nt][3]);
        }
    }
}

// ---------------- kernel 3: attention (flash-style, cp.async 2-stage) --------
// smem floats: [0,12288) stage0 K|V, [12288,24576) stage1 K|V,
//              [24576,24704) mask[2][64] (ints), [24704,25216) sML. cAcc aliases stage0.
#define ATTN_SMEM_BYTES (25216 * 4)

__global__ void __launch_bounds__(256) attn_kernel(const int* __restrict__ mask)
{
    extern __shared__ float sm[];
    int*   sMaskAll = (int*)(sm + 24576);
    float* sML  = sm + 24704;
    float* cAcc = sm;

    int t = blockIdx.x >> 2;
    if (t >= g_numTiles) return;
    int hp = blockIdx.x & 3;
    int b = g_tile_b[t], n0 = g_tile_n0[t], nv = g_tile_nv[t];
    int tid = threadIdx.x, w = tid >> 5, lane = tid & 31;
    int hl = w & 1, st = w >> 1;
    int h = hp * 2 + hl;

    float qv[48];
    if (lane < nv) {
        const float4* qp = (const float4*)&g_q[(n0 + lane) * HDH + h * D_HEAD];
#pragma unroll
        for (int i = 0; i < 12; i++) {
            float4 v = qp[i];
            qv[4 * i] = v.x; qv[4 * i + 1] = v.y; qv[4 * i + 2] = v.z; qv[4 * i + 3] = v.w;
        }
    } else {
#pragma unroll
        for (int i = 0; i < 48; i++) qv[i] = 0.f;
    }

    float m = -1e30f, l = 0.f;
    float acc[48];
#pragma unroll
    for (int i = 0; i < 48; i++) acc[i] = 0.f;

    uint32_t sb = smem_u32(sm);
    const char* Kg = (const char*)g_k;
    const char* Vg = (const char*)g_v;

    // per-thread copy slots (6 K + 6 V float4s per stage)
    uint32_t so16[6];
    long     gOff[6];
#pragma unroll
    for (int q8 = 0; q8 < 6; q8++) {
        int idx = tid + q8 * 256;
        int row = idx / 24, c4 = idx % 24;
        so16[q8] = (uint32_t)(row * 24 + c4) * 16;
        gOff[q8] = ((long)(b * S_LEN + row) * 96 + hp * 24 + c4) * 16;
    }
    const char* maskSrc = (const char*)(mask + (long)b * S_LEN + tid * 4);

    // prologue: chunks 0,1
#pragma unroll
    for (int cj = 0; cj < 2; cj++) {
        uint32_t kb = sb + (uint32_t)(cj * 12288) * 4;
        long chOff = (long)cj * 64 * 96 * 16;
#pragma unroll
        for (int q8 = 0; q8 < 6; q8++) {
            CP16(kb + so16[q8], Kg + gOff[q8] + chOff);
            CP16(kb + 6144 * 4 + so16[q8], Vg + gOff[q8] + chOff);
        }
        if (tid < 16)
            CP16(sb + (uint32_t)(24576 + cj * 64) * 4 + tid * 16,
                 maskSrc + (long)cj * 256);
        CP_COMMIT();
    }

    for (int ci = 0; ci < 16; ci++) {
        CP_WAIT1();
        __syncthreads();
        const float* sK = sm + (ci & 1) * 12288;
        const float* sV = sK + 6144;
        const int* sMask = sMaskAll + (ci & 1) * 64;

        float sc16[16];
#pragma unroll 4
        for (int i = 0; i < 16; i++) {
            int s = 4 * i + st;
            if (sMask[s]) {
                const float4* kr = (const float4*)&sK[s * 96 + hl * 48];
                float d0 = 0.f, d1 = 0.f, d2 = 0.f, d3 = 0.f;
#pragma unroll
                for (int i4 = 0; i4 < 12; i4++) {
                    float4 kk = kr[i4];
                    d0 = fmaf(qv[4 * i4 + 0], kk.x, d0);
                    d1 = fmaf(qv[4 * i4 + 1], kk.y, d1);
                    d2 = fmaf(qv[4 * i4 + 2], kk.z, d2);
                    d3 = fmaf(qv[4 * i4 + 3], kk.w, d3);
                }
                sc16[i] = ((d0 + d1) + (d2 + d3)) * INV_SCALE;
            } else {
                sc16[i] = -1e30f;
            }
        }
        float mc = -1e30f;
#pragma unroll
        for (int i = 0; i < 16; i++) mc = fmaxf(mc, sc16[i]);
        if (mc > -1e29f) {
            float mn = fmaxf(m, mc);
            float f = __expf(m - mn);
            l *= f;
#pragma unroll
            for (int d = 0; d < 48; d++) acc[d] *= f;
            m = mn;
#pragma unroll 2
            for (int i = 0; i < 16; i++) {
                if (sc16[i] > -1e29f) {
                    float p = __expf(sc16[i] - m);
                    l += p;
                    const float4* vr = (const float4*)&sV[(4 * i + st) * 96 + hl * 48];
#pragma unroll
                    for (int i4 = 0; i4 < 12; i4++) {
                        float4 vv = vr[i4];
                        acc[4 * i4 + 0] = fmaf(p, vv.x, acc[4 * i4 + 0]);
                        acc[4 * i4 + 1] = fmaf(p, vv.y, acc[4 * i4 + 1]);
                        acc[4 * i4 + 2] = fmaf(p, vv.z, acc[4 * i4 + 2]);
                        acc[4 * i4 + 3] = fmaf(p, vv.w, acc[4 * i4 + 3]);
                    }
                }
            }
        }
        __syncthreads();
        if (ci < 14) {
            int cj = ci + 2;
            uint32_t kb = sb + (uint32_t)((cj & 1) * 12288) * 4;
            long chOff = (long)cj * 64 * 96 * 16;
#pragma unroll
            for (int q8 = 0; q8 < 6; q8++) {
                CP16(kb + so16[q8], Kg + gOff[q8] + chOff);
                CP16(kb + 6144 * 4 + so16[q8], Vg + gOff[q8] + chOff);
            }
            if (tid < 16)
                CP16(sb + (uint32_t)(24576 + (cj & 1) * 64) * 4 + tid * 16,
                     maskSrc + (long)cj * 256);
        }
        CP_COMMIT();
    }
    CP_WAIT0();
    __syncthreads();

    // publish per-stripe partials (cAcc aliases stage0 smem)
    {
        int r = (st * 32 + lane) * 2 + hl;
        sML[r * 2 + 0] = m;
        sML[r * 2 + 1] = l;
#pragma unroll
        for (int d = 0; d < 48; d++) cAcc[r * 48 + d] = acc[d];
    }
    __syncthreads();

    if (tid < 64) {
        int j = tid >> 1, hlf = tid & 1;
        int hf = hp * 2 + hlf;
        float M = -1e30f;
#pragma unroll
        for (int s = 0; s < 4; s++)
            M = fmaxf(M, sML[((s * 32 + j) * 2 + hlf) * 2]);
        float L = 0.f, e[4];
#pragma unroll
        for (int s = 0; s < 4; s++) {
            float ms = sML[((s * 32 + j) * 2 + hlf) * 2];
            float ls = sML[((s * 32 + j) * 2 + hlf) * 2 + 1];
            e[s] = __expf(ms - M);
            L += ls * e[s];
        }
        float invL = 1.f / (L + 1e-9f);
        if (j < nv) {
            float* outp = &g_feat[(n0 + j) * HDH + hf * D_HEAD];
            for (int d = 0; d < 48; d++) {
                float F = 0.f;
#pragma unroll
                for (int s = 0; s < 4; s++)
                    F += cAcc[((s * 32 + j) * 2 + hlf) * 48 + d] * e[s];
                outp[d] = F * invL;
            }
        }
    }
}

// ---------------- kernel 4: gate * feat @ Wback + residual -------------------
__global__ void __launch_bounds__(256) out_kernel(
    const float* __restrict__ node, const float* __restrict__ Wback,
    const float* __restrict__ bback, float* __restrict__ out)
{
    __shared__ float sx[8][HDH];
    int n0 = blockIdx.x * 8;
    int tid = threadIdx.x;
    for (int idx = tid; idx < 8 * HDH; idx += 256) {
        int j = idx / HDH, cc = idx % HDH;
        float gpre = g_gpre[(n0 + j) * HDH + cc];
        float gate = 1.f / (1.f + __expf(-gpre));
        sx[j][cc] = gate * g_feat[(n0 + j) * HDH + cc];
    }
    __syncthreads();

    int col = tid;
    float a[8];
#pragma unroll
    for (int j = 0; j < 8; j++) a[j] = 0.f;
    for (int cc = 0; cc < HDH; cc++) {
        float wb = Wback[cc * DIM + col];
#pragma unroll
        for (int j = 0; j < 8; j++) a[j] = fmaf(sx[j][cc], wb, a[j]);
    }
    float bb = bback[col];
#pragma unroll
    for (int j = 0; j < 8; j++)
        out[(n0 + j) * DIM + col] = node[(n0 + j) * DIM + col] + a[j] + bb;
}

// ---------------- launch -----------------------------------------------------
extern "C" void kernel_launch(void* const* d_in, const int* in_sizes, int n_in,
                              void* d_out, int out_size) {
    const float* node  = (const float*)d_in[0];
    const float* emb   = (const float*)d_in[1];
    const int*   mask  = (const int*)d_in[2];
    const void*  batch = d_in[3];
    const float* ln_g  = (const float*)d_in[4];
    const float* ln_b  = (const float*)d_in[5];
    const float* Wq    = (const float*)d_in[6];
    const float* Wk    = (const float*)d_in[7];
    const float* Wv    = (const float*)d_in[8];
    const float* Wg    = (const float*)d_in[9];
    const float* bg    = (const float*)d_in[10];
    const float* Wback = (const float*)d_in[11];
    const float* bback = (const float*)d_in[12];
    float* out = (float*)d_out;

    cudaFuncSetAttribute(attn_kernel,
                         cudaFuncAttributeMaxDynamicSharedMemorySize, ATTN_SMEM_BYTES);
    cudaFuncSetAttribute(kv_mma_kernel,
                         cudaFuncAttributeMaxDynamicSharedMemorySize, KV_SMEM_BYTES);

    setup_kernel<<<1, 256>>>(batch);
    cvt_kernel<<<8192 * D_SEQ / 1024, 256>>>(emb);
    wt_kernel<<<dim3(D_SEQ / 32, 768 / 32), 256>>>(Wk, Wv);
    lnqg_kernel<<<N_NODE / 8, 384>>>(node, ln_g, ln_b, Wq, Wg, bg);
    kv_mma_kernel<<<dim3(64, 12), 256, KV_SMEM_BYTES>>>();
    attn_kernel<<<288, 256, ATTN_SMEM_BYTES>>>(mask);
    out_kernel<<<N_NODE / 8, 256>>>(node, Wback, bback, out);
}

// round 12
// speedup vs baseline: 1.8783x; 1.1797x over previous
#include <cuda_runtime.h>
#include <cstdint>

#define N_NODE 2048
#define DIM 256
#define D_SEQ 1280
#define HDH 384
#define N_HEAD 8
#define D_HEAD 48
#define B_GRAPH 8
#define S_LEN 1024
#define INV_SCALE 0.14433756729740643f  /* 1/sqrt(48) */

// ---------------- scratch (device globals; no allocs allowed) ----------------
__device__ __align__(128) float g_k[B_GRAPH * S_LEN * HDH];    // [b,s,h,d]
__device__ __align__(128) float g_v[B_GRAPH * S_LEN * HDH];
__device__ __align__(128) float g_q[N_NODE * HDH];
__device__ __align__(128) float g_gpre[N_NODE * HDH];
__device__ __align__(128) float g_feat[N_NODE * HDH];
__device__ __align__(128) float g_y[N_NODE * DIM];             // tf32-rounded LN(node)
__device__ __align__(128) float g_gf[N_NODE * HDH];            // tf32-rounded gate*feat
__device__ __align__(128) float g_wt[768 * D_SEQ];             // [n,k] tf32 [Wk|Wv]^T
__device__ __align__(128) float g_wqg[768 * DIM];              // [n,k] tf32 [Wq|Wg]^T
__device__ __align__(128) float g_wbt[DIM * HDH];              // [n,k] tf32 Wback^T
__device__ __align__(128) float g_embt[8192 * D_SEQ];          // tf32-rounded emb
__device__ int   g_numTiles;
__device__ int   g_tile_b[80];
__device__ int   g_tile_n0[80];
__device__ int   g_tile_nv[80];

__device__ __forceinline__ uint32_t smem_u32(const void* p) {
    uint32_t a;
    asm("{ .reg .u64 t; cvta.to.shared.u64 t, %1; cvt.u32.u64 %0, t; }"
        : "=r"(a) : "l"(p));
    return a;
}
__device__ __forceinline__ uint32_t to_tf32(float f) {
    uint32_t o;
    asm("cvt.rna.tf32.f32 %0, %1;" : "=r"(o) : "f"(f));
    return o;
}
__device__ __forceinline__ float round_tf32(float f) {
    return __uint_as_float(to_tf32(f));
}
#define CP16(dst, src) \
    asm volatile("cp.async.cg.shared.global [%0], [%1], 16;" \
                 :: "r"(dst), "l"(src) : "memory")
#define CP_COMMIT() asm volatile("cp.async.commit_group;" ::: "memory")
#define CP_WAIT1()  asm volatile("cp.async.wait_group 1;" ::: "memory")
#define CP_WAIT0()  asm volatile("cp.async.wait_group 0;" ::: "memory")

// ---------------- kernel 0: segment batch, build node tiles ------------------
__global__ void setup_kernel(const void* batch_raw) {
    __shared__ int cnt[8];
    __shared__ int ok32;
    int tid = threadIdx.x;
    if (tid < 8) cnt[tid] = 0;
    if (tid == 0) ok32 = 1;
    __syncthreads();
    const int* b32 = (const int*)batch_raw;
    int bad = 0;
    for (int i = tid; i < N_NODE; i += blockDim.x) {
        int v = b32[i];
        if (v < 0 || v >= 8) bad = 1;
        if (i + 1 < N_NODE && b32[i + 1] < v) bad = 1;
    }
    if (bad) ok32 = 0;
    __syncthreads();
    const long long* b64 = (const long long*)batch_raw;
    for (int i = tid; i < N_NODE; i += blockDim.x) {
        int v = ok32 ? b32[i] : (int)b64[i];
        v = min(max(v, 0), 7);
        atomicAdd(&cnt[v], 1);
    }
    __syncthreads();
    if (tid == 0) {
        int off = 0, t = 0;
        for (int b = 0; b < 8; b++) {
            int nb = cnt[b];
            for (int s = 0; s < nb; s += 32) {
                g_tile_b[t] = b;
                g_tile_n0[t] = off + s;
                g_tile_nv[t] = min(32, nb - s);
                t++;
            }
            off += nb;
        }
        g_numTiles = t;
    }
}

// ---------------- kernel 0a: round emb to tf32 (rna) -> g_embt ---------------
__global__ void __launch_bounds__(256) cvt_kernel(const float* __restrict__ emb) {
    int i = blockIdx.x * 256 + threadIdx.x;   // float4 index; grid covers exactly
    float4 v = ((const float4*)emb)[i];
    float4 o;
    o.x = round_tf32(v.x); o.y = round_tf32(v.y);
    o.z = round_tf32(v.z); o.w = round_tf32(v.w);
    ((float4*)g_embt)[i] = o;
}

// ------------ kernel 0b: generic transpose + tf32 round ----------------------
// src[R][C] row-major -> dst[(rowOff+c)][r], dst row stride = R. R,C mult of 32.
__global__ void __launch_bounds__(256) transpose_round(
    const float* __restrict__ src, int R, int C,
    float* __restrict__ dst, int rowOff)
{
    __shared__ float tile[32][33];
    int kb = blockIdx.x * 32, nb = blockIdx.y * 32;   // kb over R, nb over C
    int tx = threadIdx.x & 31, ty = threadIdx.x >> 5; // 32 x 8
#pragma unroll
    for (int i = 0; i < 4; i++)
        tile[ty + i * 8][tx] = src[(size_t)(kb + ty + i * 8) * C + nb + tx];
    __syncthreads();
#pragma unroll
    for (int i = 0; i < 4; i++)
        dst[(size_t)(rowOff + nb + ty + i * 8) * R + kb + tx] =
            round_tf32(tile[tx][ty + i * 8]);
}

// ---------------- kernel 1: layernorm -> g_y (tf32-rounded) ------------------
__global__ void __launch_bounds__(256) ln_kernel(
    const float* __restrict__ node,
    const float* __restrict__ ln_g, const float* __restrict__ ln_b)
{
    int w = threadIdx.x >> 5, lane = threadIdx.x & 31;
    int n = blockIdx.x * 8 + w;
    float xv[8];
    float sx = 0.f, sxx = 0.f;
#pragma unroll
    for (int i = 0; i < 8; i++) {
        float x = node[n * DIM + lane + i * 32];
        xv[i] = x; sx += x; sxx += x * x;
    }
#pragma unroll
    for (int o = 16; o > 0; o >>= 1) {
        sx  += __shfl_xor_sync(0xffffffffu, sx, o);
        sxx += __shfl_xor_sync(0xffffffffu, sxx, o);
    }
    float mu = sx * (1.f / DIM);
    float var = sxx * (1.f / DIM) - mu * mu;
    float inv = rsqrtf(var + 1e-5f);
#pragma unroll
    for (int i = 0; i < 8; i++) {
        int d = lane + i * 32;
        g_y[n * DIM + d] = round_tf32((xv[i] - mu) * inv * ln_g[d] + ln_b[d]);
    }
}

// ---------------- kernel 1b: gate*feat -> g_gf (tf32-rounded) ----------------
__global__ void __launch_bounds__(256) gf_kernel() {
    int i = blockIdx.x * 256 + threadIdx.x;   // float4 index, grid covers exactly
    float4 gp = ((const float4*)g_gpre)[i];
    float4 ft = ((const float4*)g_feat)[i];
    float4 o;
    o.x = round_tf32(ft.x / (1.f + __expf(-gp.x)));
    o.y = round_tf32(ft.y / (1.f + __expf(-gp.y)));
    o.z = round_tf32(ft.z / (1.f + __expf(-gp.z)));
    o.w = round_tf32(ft.w / (1.f + __expf(-gp.w)));
    ((float4*)g_gf)[i] = o;
}

// ---------------- unified TF32 mma.sync GEMM ---------------------------------
// C[M,64*gy] tile per CTA: 128x64, 8 warps (4m x 2n), warp 32x32, 2-stage
// cp.async. A[M,K], B[N,K] both row-major, K-major, tf32-pre-rounded.
// EPI 0: split cols at 384 -> p0 (g_k) / p1 (g_v), stride HDH
// EPI 1: split cols at 384 -> p0 (g_q) / p1 (g_gpre, + bias q0), stride HDH
// EPI 2: p0[r*256+c] = q0[r*256+c] + acc + q1[c]   (out = node + new + bback)
#define KV_STRIDE 36
#define KV_STAGE_U32 ((128 + 64) * KV_STRIDE)   // 6912 u32 = 27648 B
#define KV_SMEM_BYTES (2 * KV_STAGE_U32 * 4)    // 55296 B

#define MMA_TF32(c, a, b) \
    asm volatile("mma.sync.aligned.m16n8k8.row.col.f32.tf32.tf32.f32 " \
        "{%0,%1,%2,%3}, {%4,%5,%6,%7}, {%8,%9}, {%0,%1,%2,%3};" \
        : "+f"((c)[0]), "+f"((c)[1]), "+f"((c)[2]), "+f"((c)[3]) \
        : "r"((a)[0]), "r"((a)[1]), "r"((a)[2]), "r"((a)[3]), \
          "r"((b)[0]), "r"((b)[1]))

template<int CHUNKS, int EPI>
__global__ void __launch_bounds__(256, 4) gemm_tf32(
    const float* __restrict__ A, const float* __restrict__ B,
    float* __restrict__ p0, float* __restrict__ p1,
    const float* __restrict__ q0, const float* __restrict__ q1)
{
    const int K = CHUNKS * 32;
    extern __shared__ uint32_t skv[];
    uint32_t sb = smem_u32(skv);

    int tid = threadIdx.x;
    int wid = tid >> 5, lane = tid & 31;
    int warp_m = wid & 3, warp_n = wid >> 2;
    int lr = lane >> 2, lc = lane & 3;

    int m0 = (int)blockIdx.x * 128;
    int n0 = (int)blockIdx.y * 64;

    int arow = tid >> 1, ahalf = tid & 1;                 // A: 4 cp16 / thread
    const char* gA = (const char*)(A + (size_t)(m0 + arow) * K + ahalf * 16);
    int brow = tid >> 2, bq = tid & 3;                    // B: 2 cp16 / thread
    const char* gB = (const char*)(B + (size_t)(n0 + brow) * K + bq * 8);
    uint32_t dA = sb + (uint32_t)(arow * KV_STRIDE + ahalf * 16) * 4;
    uint32_t dB = sb + (uint32_t)(128 * KV_STRIDE + brow * KV_STRIDE + bq * 8) * 4;

    float acc[2][4][4];
#pragma unroll
    for (int mt = 0; mt < 2; mt++)
#pragma unroll
        for (int nt = 0; nt < 4; nt++)
#pragma unroll
            for (int i = 0; i < 4; i++) acc[mt][nt][i] = 0.f;

    // prologue: chunks 0,1
#pragma unroll
    for (int st = 0; st < 2; st++) {
        uint32_t off = st * (KV_STAGE_U32 * 4);
        int kb = st * 32 * 4;  // bytes
#pragma unroll
        for (int j = 0; j < 4; j++) CP16(dA + off + j * 16, gA + kb + j * 16);
#pragma unroll
        for (int j = 0; j < 2; j++) CP16(dB + off + j * 16, gB + kb + j * 16);
        CP_COMMIT();
    }

    for (int ch = 0; ch < CHUNKS; ch++) {
        CP_WAIT1();
        __syncthreads();
        const uint32_t* sA = skv + (ch & 1) * KV_STAGE_U32;
        const uint32_t* sBp = sA + 128 * KV_STRIDE;

#pragma unroll
        for (int ks = 0; ks < 4; ks++) {
            int kk = ks * 8;
            uint32_t af[2][4];
#pragma unroll
            for (int mt = 0; mt < 2; mt++) {
                int r = warp_m * 32 + mt * 16 + lr;
                int c = kk + lc;
                af[mt][0] = sA[r * KV_STRIDE + c];
                af[mt][1] = sA[(r + 8) * KV_STRIDE + c];
                af[mt][2] = sA[r * KV_STRIDE + c + 4];
                af[mt][3] = sA[(r + 8) * KV_STRIDE + c + 4];
            }
            uint32_t bf[4][2];
#pragma unroll
            for (int nt = 0; nt < 4; nt++) {
                int n = warp_n * 32 + nt * 8 + lr;
                bf[nt][0] = sBp[n * KV_STRIDE + kk + lc];
                bf[nt][1] = sBp[n * KV_STRIDE + kk + lc + 4];
            }
#pragma unroll
            for (int mt = 0; mt < 2; mt++)
#pragma unroll
                for (int nt = 0; nt < 4; nt++)
                    MMA_TF32(acc[mt][nt], af[mt], bf[nt]);
        }
        __syncthreads();
        if (ch < CHUNKS - 2) {
            uint32_t off = (ch & 1) * (KV_STAGE_U32 * 4);
            int kb = (ch + 2) * 32 * 4;  // bytes
#pragma unroll
            for (int j = 0; j < 4; j++) CP16(dA + off + j * 16, gA + kb + j * 16);
#pragma unroll
            for (int j = 0; j < 2; j++) CP16(dB + off + j * 16, gB + kb + j * 16);
        }
        CP_COMMIT();
    }

    // epilogue
#pragma unroll
    for (int mt = 0; mt < 2; mt++) {
        int r = m0 + warp_m * 32 + mt * 16 + lr;
#pragma unroll
        for (int nt = 0; nt < 4; nt++) {
            int cn = n0 + warp_n * 32 + nt * 8 + 2 * lc;
            float2 lo = make_float2(acc[mt][nt][0], acc[mt][nt][1]);
            float2 hi = make_float2(acc[mt][nt][2], acc[mt][nt][3]);
            if (EPI == 0) {          // k | v
                float* dst = (n0 < 384) ? p0 : p1;
                int c = (n0 < 384) ? cn : cn - 384;
                *(float2*)&dst[(size_t)r * HDH + c] = lo;
                *(float2*)&dst[(size_t)(r + 8) * HDH + c] = hi;
            } else if (EPI == 1) {   // q | gpre(+bg)
                if (n0 < 384) {
                    *(float2*)&p0[(size_t)r * HDH + cn] = lo;
                    *(float2*)&p0[(size_t)(r + 8) * HDH + cn] = hi;
                } else {
                    int c = cn - 384;
                    float2 bb = *(const float2*)&q0[c];
                    lo.x += bb.x; lo.y += bb.y; hi.x += bb.x; hi.y += bb.y;
                    *(float2*)&p1[(size_t)r * HDH + c] = lo;
                    *(float2*)&p1[(size_t)(r + 8) * HDH + c] = hi;
                }
            } else {                 // out = node + acc + bback
                float2 bb = *(const float2*)&q1[cn];
                float2 n1 = *(const float2*)&q0[(size_t)r * DIM + cn];
                float2 n2 = *(const float2*)&q0[(size_t)(r + 8) * DIM + cn];
                lo.x += bb.x + n1.x; lo.y += bb.y + n1.y;
                hi.x += bb.x + n2.x; hi.y += bb.y + n2.y;
                *(float2*)&p0[(size_t)r * DIM + cn] = lo;
                *(float2*)&p0[(size_t)(r + 8) * DIM + cn] = hi;
            }
        }
    }
}

// ---------------- kernel 3: attention (flash-style, cp.async 2-stage) --------
#define ATTN_SMEM_BYTES (25216 * 4)

__global__ void __launch_bounds__(256) attn_kernel(const int* __restrict__ mask)
{
    extern __shared__ float sm[];
    int*   sMaskAll = (int*)(sm + 24576);
    float* sML  = sm + 24704;
    float* cAcc = sm;

    int t = blockIdx.x >> 2;
    if (t >= g_numTiles) return;
    int hp = blockIdx.x & 3;
    int b = g_tile_b[t], n0 = g_tile_n0[t], nv = g_tile_nv[t];
    int tid = threadIdx.x, w = tid >> 5, lane = tid & 31;
    int hl = w & 1, st = w >> 1;
    int h = hp * 2 + hl;

    float qv[48];
    if (lane < nv) {
        const float4* qp = (const float4*)&g_q[(n0 + lane) * HDH + h * D_HEAD];
#pragma unroll
        for (int i = 0; i < 12; i++) {
            float4 v = qp[i];
            qv[4 * i] = v.x; qv[4 * i + 1] = v.y; qv[4 * i + 2] = v.z; qv[4 * i + 3] = v.w;
        }
    } else {
#pragma unroll
        for (int i = 0; i < 48; i++) qv[i] = 0.f;
    }

    float m = -1e30f, l = 0.f;
    float acc[48];
#pragma unroll
    for (int i = 0; i < 48; i++) acc[i] = 0.f;

    uint32_t sb = smem_u32(sm);
    const char* Kg = (const char*)g_k;
    const char* Vg = (const char*)g_v;

    uint32_t so16[6];
    long     gOff[6];
#pragma unroll
    for (int q8 = 0; q8 < 6; q8++) {
        int idx = tid + q8 * 256;
        int row = idx / 24, c4 = idx % 24;
        so16[q8] = (uint32_t)(row * 24 + c4) * 16;
        gOff[q8] = ((long)(b * S_LEN + row) * 96 + hp * 24 + c4) * 16;
    }
    const char* maskSrc = (const char*)(mask + (long)b * S_LEN + tid * 4);

#pragma unroll
    for (int cj = 0; cj < 2; cj++) {
        uint32_t kb = sb + (uint32_t)(cj * 12288) * 4;
        long chOff = (long)cj * 64 * 96 * 16;
#pragma unroll
        for (int q8 = 0; q8 < 6; q8++) {
            CP16(kb + so16[q8], Kg + gOff[q8] + chOff);
            CP16(kb + 6144 * 4 + so16[q8], Vg + gOff[q8] + chOff);
        }
        if (tid < 16)
            CP16(sb + (uint32_t)(24576 + cj * 64) * 4 + tid * 16,
                 maskSrc + (long)cj * 256);
        CP_COMMIT();
    }

    for (int ci = 0; ci < 16; ci++) {
        CP_WAIT1();
        __syncthreads();
        const float* sK = sm + (ci & 1) * 12288;
        const float* sV = sK + 6144;
        const int* sMask = sMaskAll + (ci & 1) * 64;

        float sc16[16];
#pragma unroll 4
        for (int i = 0; i < 16; i++) {
            int s = 4 * i + st;
            if (sMask[s]) {
                const float4* kr = (const float4*)&sK[s * 96 + hl * 48];
                float d0 = 0.f, d1 = 0.f, d2 = 0.f, d3 = 0.f;
#pragma unroll
                for (int i4 = 0; i4 < 12; i4++) {
                    float4 kk = kr[i4];
                    d0 = fmaf(qv[4 * i4 + 0], kk.x, d0);
                    d1 = fmaf(qv[4 * i4 + 1], kk.y, d1);
                    d2 = fmaf(qv[4 * i4 + 2], kk.z, d2);
                    d3 = fmaf(qv[4 * i4 + 3], kk.w, d3);
                }
                sc16[i] = ((d0 + d1) + (d2 + d3)) * INV_SCALE;
            } else {
                sc16[i] = -1e30f;
            }
        }
        float mc = -1e30f;
#pragma unroll
        for (int i = 0; i < 16; i++) mc = fmaxf(mc, sc16[i]);
        if (mc > -1e29f) {
            float mn = fmaxf(m, mc);
            float f = __expf(m - mn);
            l *= f;
#pragma unroll
            for (int d = 0; d < 48; d++) acc[d] *= f;
            m = mn;
#pragma unroll 2
            for (int i = 0; i < 16; i++) {
                if (sc16[i] > -1e29f) {
                    float p = __expf(sc16[i] - m);
                    l += p;
                    const float4* vr = (const float4*)&sV[(4 * i + st) * 96 + hl * 48];
#pragma unroll
                    for (int i4 = 0; i4 < 12; i4++) {
                        float4 vv = vr[i4];
                        acc[4 * i4 + 0] = fmaf(p, vv.x, acc[4 * i4 + 0]);
                        acc[4 * i4 + 1] = fmaf(p, vv.y, acc[4 * i4 + 1]);
                        acc[4 * i4 + 2] = fmaf(p, vv.z, acc[4 * i4 + 2]);
                        acc[4 * i4 + 3] = fmaf(p, vv.w, acc[4 * i4 + 3]);
                    }
                }
            }
        }
        __syncthreads();
        if (ci < 14) {
            int cj = ci + 2;
            uint32_t kb = sb + (uint32_t)((cj & 1) * 12288) * 4;
            long chOff = (long)cj * 64 * 96 * 16;
#pragma unroll
            for (int q8 = 0; q8 < 6; q8++) {
                CP16(kb + so16[q8], Kg + gOff[q8] + chOff);
                CP16(kb + 6144 * 4 + so16[q8], Vg + gOff[q8] + chOff);
            }
            if (tid < 16)
                CP16(sb + (uint32_t)(24576 + (cj & 1) * 64) * 4 + tid * 16,
                     maskSrc + (long)cj * 256);
        }
        CP_COMMIT();
    }
    CP_WAIT0();
    __syncthreads();

    {
        int r = (st * 32 + lane) * 2 + hl;
        sML[r * 2 + 0] = m;
        sML[r * 2 + 1] = l;
#pragma unroll
        for (int d = 0; d < 48; d++) cAcc[r * 48 + d] = acc[d];
    }
    __syncthreads();

    if (tid < 64) {
        int j = tid >> 1, hlf = tid & 1;
        int hf = hp * 2 + hlf;
        float M = -1e30f;
#pragma unroll
        for (int s = 0; s < 4; s++)
            M = fmaxf(M, sML[((s * 32 + j) * 2 + hlf) * 2]);
        float L = 0.f, e[4];
#pragma unroll
        for (int s = 0; s < 4; s++) {
            float ms = sML[((s * 32 + j) * 2 + hlf) * 2];
            float ls = sML[((s * 32 + j) * 2 + hlf) * 2 + 1];
            e[s] = __expf(ms - M);
            L += ls * e[s];
        }
        float invL = 1.f / (L + 1e-9f);
        if (j < nv) {
            float* outp = &g_feat[(n0 + j) * HDH + hf * D_HEAD];
            for (int d = 0; d < 48; d++) {
                float F = 0.f;
#pragma unroll
                for (int s = 0; s < 4; s++)
                    F += cAcc[((s * 32 + j) * 2 + hlf) * 48 + d] * e[s];
                outp[d] = F * invL;
            }
        }
    }
}

// ---------------- launch -----------------------------------------------------
extern "C" void kernel_launch(void* const* d_in, const int* in_sizes, int n_in,
                              void* d_out, int out_size) {
    const float* node  = (const float*)d_in[0];
    const float* emb   = (const float*)d_in[1];
    const int*   mask  = (const int*)d_in[2];
    const void*  batch = d_in[3];
    const float* ln_g  = (const float*)d_in[4];
    const float* ln_b  = (const float*)d_in[5];
    const float* Wq    = (const float*)d_in[6];
    const float* Wk    = (const float*)d_in[7];
    const float* Wv    = (const float*)d_in[8];
    const float* Wg    = (const float*)d_in[9];
    const float* bg    = (const float*)d_in[10];
    const float* Wback = (const float*)d_in[11];
    const float* bback = (const float*)d_in[12];
    float* out = (float*)d_out;

    // device-global symbol addresses (host side)
    float *p_q, *p_gpre, *p_k, *p_v, *p_y, *p_gf, *p_wt, *p_wqg, *p_wbt, *p_embt;
    cudaGetSymbolAddress((void**)&p_q,    g_q);
    cudaGetSymbolAddress((void**)&p_gpre, g_gpre);
    cudaGetSymbolAddress((void**)&p_k,    g_k);
    cudaGetSymbolAddress((void**)&p_v,    g_v);
    cudaGetSymbolAddress((void**)&p_y,    g_y);
    cudaGetSymbolAddress((void**)&p_gf,   g_gf);
    cudaGetSymbolAddress((void**)&p_wt,   g_wt);
    cudaGetSymbolAddress((void**)&p_wqg,  g_wqg);
    cudaGetSymbolAddress((void**)&p_wbt,  g_wbt);
    cudaGetSymbolAddress((void**)&p_embt, g_embt);

    cudaFuncSetAttribute(attn_kernel,
                         cudaFuncAttributeMaxDynamicSharedMemorySize, ATTN_SMEM_BYTES);
    cudaFuncSetAttribute(gemm_tf32<8, 1>,
                         cudaFuncAttributeMaxDynamicSharedMemorySize, KV_SMEM_BYTES);
    cudaFuncSetAttribute(gemm_tf32<40, 0>,
                         cudaFuncAttributeMaxDynamicSharedMemorySize, KV_SMEM_BYTES);
    cudaFuncSetAttribute(gemm_tf32<12, 2>,
                         cudaFuncAttributeMaxDynamicSharedMemorySize, KV_SMEM_BYTES);

    setup_kernel<<<1, 256>>>(batch);
    cvt_kernel<<<8192 * D_SEQ / 1024, 256>>>(emb);
    // B-operand transposes (tf32-rounded, [n][k] layout)
    transpose_round<<<dim3(DIM / 32, HDH / 32), 256>>>(Wq, DIM, HDH, p_wqg, 0);
    transpose_round<<<dim3(DIM / 32, HDH / 32), 256>>>(Wg, DIM, HDH, p_wqg, 384);
    transpose_round<<<dim3(D_SEQ / 32, HDH / 32), 256>>>(Wk, D_SEQ, HDH, p_wt, 0);
    transpose_round<<<dim3(D_SEQ / 32, HDH / 32), 256>>>(Wv, D_SEQ, HDH, p_wt, 384);
    transpose_round<<<dim3(HDH / 32, DIM / 32), 256>>>(Wback, HDH, DIM, p_wbt, 0);
    ln_kernel<<<N_NODE / 8, 256>>>(node, ln_g, ln_b);
    // GEMM1: [q|gpre] = y @ [Wq|Wg]  (+bg on gpre half)
    gemm_tf32<8, 1><<<dim3(16, 12), 256, KV_SMEM_BYTES>>>(
        p_y, p_wqg, p_q, p_gpre, bg, nullptr);
    // GEMM2: [k|v] = embt @ [Wk|Wv]
    gemm_tf32<40, 0><<<dim3(64, 12), 256, KV_SMEM_BYTES>>>(
        p_embt, p_wt, p_k, p_v, nullptr, nullptr);
    attn_kernel<<<288, 256, ATTN_SMEM_BYTES>>>(mask);
    gf_kernel<<<N_NODE * HDH / 1024, 256>>>();
    // GEMM3: out = node + (gate*feat) @ Wback + bback
    gemm_tf32<12, 2><<<dim3(16, 4), 256, KV_SMEM_BYTES>>>(
        p_gf, p_wbt, out, nullptr, node, bback);
}

// round 13
// speedup vs baseline: 2.6133x; 1.3913x over previous
#include <cuda_runtime.h>
#include <cuda_bf16.h>
#include <cstdint>

#define N_NODE 2048
#define DIM 256
#define D_SEQ 1280
#define HDH 384
#define N_HEAD 8
#define D_HEAD 48
#define B_GRAPH 8
#define S_LEN 1024
#define INV_SCALE 0.14433756729740643f  /* 1/sqrt(48) */

typedef __nv_bfloat16 bf16;

// ---------------- scratch (device globals; no allocs allowed) ----------------
__device__ __align__(128) float g_k[B_GRAPH * S_LEN * HDH];    // [b,s,h,d] fp32
__device__ __align__(128) float g_v[B_GRAPH * S_LEN * HDH];
__device__ __align__(128) float g_q[N_NODE * HDH];
__device__ __align__(128) float g_gpre[N_NODE * HDH];
__device__ __align__(128) float g_feat[N_NODE * HDH];
__device__ __align__(128) bf16  g_y[N_NODE * DIM];             // bf16 LN(node)
__device__ __align__(128) bf16  g_gf[N_NODE * HDH];            // bf16 gate*feat
__device__ __align__(128) bf16  g_wt[768 * D_SEQ];             // [n,k] bf16 [Wk|Wv]^T
__device__ __align__(128) bf16  g_wqg[768 * DIM];              // [n,k] bf16 [Wq|Wg]^T
__device__ __align__(128) bf16  g_wbt[DIM * HDH];              // [n,k] bf16 Wback^T
__device__ __align__(128) bf16  g_embt[8192 * D_SEQ];          // bf16 emb
__device__ int   g_numTiles;
__device__ int   g_tile_b[80];
__device__ int   g_tile_n0[80];
__device__ int   g_tile_nv[80];

__device__ __forceinline__ uint32_t smem_u32(const void* p) {
    uint32_t a;
    asm("{ .reg .u64 t; cvta.to.shared.u64 t, %1; cvt.u32.u64 %0, t; }"
        : "=r"(a) : "l"(p));
    return a;
}
#define CP16(dst, src) \
    asm volatile("cp.async.cg.shared.global [%0], [%1], 16;" \
                 :: "r"(dst), "l"(src) : "memory")
#define CP_COMMIT() asm volatile("cp.async.commit_group;" ::: "memory")
#define CP_WAIT1()  asm volatile("cp.async.wait_group 1;" ::: "memory")
#define CP_WAIT0()  asm volatile("cp.async.wait_group 0;" ::: "memory")

// ---------------- kernel 0: segment batch, build node tiles ------------------
__global__ void setup_kernel(const void* batch_raw) {
    __shared__ int cnt[8];
    __shared__ int ok32;
    int tid = threadIdx.x;
    if (tid < 8) cnt[tid] = 0;
    if (tid == 0) ok32 = 1;
    __syncthreads();
    const int* b32 = (const int*)batch_raw;
    int bad = 0;
    for (int i = tid; i < N_NODE; i += blockDim.x) {
        int v = b32[i];
        if (v < 0 || v >= 8) bad = 1;
        if (i + 1 < N_NODE && b32[i + 1] < v) bad = 1;
    }
    if (bad) ok32 = 0;
    __syncthreads();
    const long long* b64 = (const long long*)batch_raw;
    for (int i = tid; i < N_NODE; i += blockDim.x) {
        int v = ok32 ? b32[i] : (int)b64[i];
        v = min(max(v, 0), 7);
        atomicAdd(&cnt[v], 1);
    }
    __syncthreads();
    if (tid == 0) {
        int off = 0, t = 0;
        for (int b = 0; b < 8; b++) {
            int nb = cnt[b];
            for (int s = 0; s < nb; s += 32) {
                g_tile_b[t] = b;
                g_tile_n0[t] = off + s;
                g_tile_nv[t] = min(32, nb - s);
                t++;
            }
            off += nb;
        }
        g_numTiles = t;
    }
}

// ---------------- kernel 0a: convert emb -> bf16 g_embt ----------------------
__global__ void __launch_bounds__(256) cvt_kernel(const float* __restrict__ emb) {
    int i = blockIdx.x * 256 + threadIdx.x;   // 8 floats / thread; grid exact
    float4 v0 = ((const float4*)emb)[2 * i];
    float4 v1 = ((const float4*)emb)[2 * i + 1];
    bf16 o[8];
    o[0] = __float2bfloat16_rn(v0.x); o[1] = __float2bfloat16_rn(v0.y);
    o[2] = __float2bfloat16_rn(v0.z); o[3] = __float2bfloat16_rn(v0.w);
    o[4] = __float2bfloat16_rn(v1.x); o[5] = __float2bfloat16_rn(v1.y);
    o[6] = __float2bfloat16_rn(v1.z); o[7] = __float2bfloat16_rn(v1.w);
    ((uint4*)g_embt)[i] = *(uint4*)o;
}

// ------------ kernel 0b: generic transpose + bf16 convert --------------------
// src[R][C] row-major fp32 -> dst[(rowOff+c)][r] bf16, dst row stride = R.
__global__ void __launch_bounds__(256) transpose_bf16(
    const float* __restrict__ src, int R, int C,
    bf16* __restrict__ dst, int rowOff)
{
    __shared__ float tile[32][33];
    int kb = blockIdx.x * 32, nb = blockIdx.y * 32;   // kb over R, nb over C
    int tx = threadIdx.x & 31, ty = threadIdx.x >> 5; // 32 x 8
#pragma unroll
    for (int i = 0; i < 4; i++)
        tile[ty + i * 8][tx] = src[(size_t)(kb + ty + i * 8) * C + nb + tx];
    __syncthreads();
#pragma unroll
    for (int i = 0; i < 4; i++)
        dst[(size_t)(rowOff + nb + ty + i * 8) * R + kb + tx] =
            __float2bfloat16_rn(tile[tx][ty + i * 8]);
}

// ---------------- kernel 1: layernorm -> g_y (bf16) --------------------------
__global__ void __launch_bounds__(256) ln_kernel(
    const float* __restrict__ node,
    const float* __restrict__ ln_g, const float* __restrict__ ln_b)
{
    int w = threadIdx.x >> 5, lane = threadIdx.x & 31;
    int n = blockIdx.x * 8 + w;
    float xv[8];
    float sx = 0.f, sxx = 0.f;
#pragma unroll
    for (int i = 0; i < 8; i++) {
        float x = node[n * DIM + lane + i * 32];
        xv[i] = x; sx += x; sxx += x * x;
    }
#pragma unroll
    for (int o = 16; o > 0; o >>= 1) {
        sx  += __shfl_xor_sync(0xffffffffu, sx, o);
        sxx += __shfl_xor_sync(0xffffffffu, sxx, o);
    }
    float mu = sx * (1.f / DIM);
    float var = sxx * (1.f / DIM) - mu * mu;
    float inv = rsqrtf(var + 1e-5f);
#pragma unroll
    for (int i = 0; i < 8; i++) {
        int d = lane + i * 32;
        g_y[n * DIM + d] =
            __float2bfloat16_rn((xv[i] - mu) * inv * ln_g[d] + ln_b[d]);
    }
}

// ---------------- kernel 1b: gate*feat -> g_gf (bf16) ------------------------
__global__ void __launch_bounds__(256) gf_kernel() {
    int i = blockIdx.x * 256 + threadIdx.x;   // 8 elems / thread; grid exact
    float4 g0 = ((const float4*)g_gpre)[2 * i];
    float4 g1 = ((const float4*)g_gpre)[2 * i + 1];
    float4 f0 = ((const float4*)g_feat)[2 * i];
    float4 f1 = ((const float4*)g_feat)[2 * i + 1];
    bf16 o[8];
    o[0] = __float2bfloat16_rn(f0.x / (1.f + __expf(-g0.x)));
    o[1] = __float2bfloat16_rn(f0.y / (1.f + __expf(-g0.y)));
    o[2] = __float2bfloat16_rn(f0.z / (1.f + __expf(-g0.z)));
    o[3] = __float2bfloat16_rn(f0.w / (1.f + __expf(-g0.w)));
    o[4] = __float2bfloat16_rn(f1.x / (1.f + __expf(-g1.x)));
    o[5] = __float2bfloat16_rn(f1.y / (1.f + __expf(-g1.y)));
    o[6] = __float2bfloat16_rn(f1.z / (1.f + __expf(-g1.z)));
    o[7] = __float2bfloat16_rn(f1.w / (1.f + __expf(-g1.w)));
    ((uint4*)g_gf)[i] = *(uint4*)o;
}

// ---------------- unified BF16 mma.sync GEMM ---------------------------------
// CTA 128x64, 8 warps (4m x 2n), warp 32x32 = 2x4 m16n8k16 tiles, 2-stage
// cp.async. A[M,K], B[N,K] bf16 row-major K-major. K chunk = 64 elems = 128B.
// Smem row = 32 u32 (bf16 pairs), stride 36 (conflict-free, same as tf32 ver).
// EPI 0: split cols at 384 -> p0 (g_k) / p1 (g_v), fp32 stride HDH
// EPI 1: split cols at 384 -> p0 (g_q) / p1 (g_gpre, + bias q0)
// EPI 2: p0[r*256+c] = q0[r*256+c] + acc + q1[c]
#define KV_STRIDE 36
#define KV_STAGE_U32 ((128 + 64) * KV_STRIDE)   // 6912 u32 = 27648 B
#define KV_SMEM_BYTES (2 * KV_STAGE_U32 * 4)    // 55296 B

#define MMA_BF16(c, a, b) \
    asm volatile("mma.sync.aligned.m16n8k16.row.col.f32.bf16.bf16.f32 " \
        "{%0,%1,%2,%3}, {%4,%5,%6,%7}, {%8,%9}, {%0,%1,%2,%3};" \
        : "+f"((c)[0]), "+f"((c)[1]), "+f"((c)[2]), "+f"((c)[3]) \
        : "r"((a)[0]), "r"((a)[1]), "r"((a)[2]), "r"((a)[3]), \
          "r"((b)[0]), "r"((b)[1]))

template<int CHUNKS, int EPI>
__global__ void __launch_bounds__(256, 4) gemm_bf16(
    const bf16* __restrict__ A, const bf16* __restrict__ B,
    float* __restrict__ p0, float* __restrict__ p1,
    const float* __restrict__ q0, const float* __restrict__ q1)
{
    const int K = CHUNKS * 64;
    extern __shared__ uint32_t skv[];
    uint32_t sb = smem_u32(skv);

    int tid = threadIdx.x;
    int wid = tid >> 5, lane = tid & 31;
    int warp_m = wid & 3, warp_n = wid >> 2;
    int lr = lane >> 2, lc = lane & 3;

    int m0 = (int)blockIdx.x * 128;
    int n0 = (int)blockIdx.y * 64;

    int arow = tid >> 1, ahalf = tid & 1;                 // A: 4 cp16 / thread
    const char* gA = (const char*)(A + (size_t)(m0 + arow) * K) + ahalf * 64;
    int brow = tid >> 2, bq = tid & 3;                    // B: 2 cp16 / thread
    const char* gB = (const char*)(B + (size_t)(n0 + brow) * K) + bq * 32;
    uint32_t dA = sb + (uint32_t)(arow * KV_STRIDE + ahalf * 16) * 4;
    uint32_t dB = sb + (uint32_t)(128 * KV_STRIDE + brow * KV_STRIDE + bq * 8) * 4;

    float acc[2][4][4];
#pragma unroll
    for (int mt = 0; mt < 2; mt++)
#pragma unroll
        for (int nt = 0; nt < 4; nt++)
#pragma unroll
            for (int i = 0; i < 4; i++) acc[mt][nt][i] = 0.f;

    // prologue: chunks 0,1  (chunk stride = 128 bytes)
#pragma unroll
    for (int st = 0; st < 2; st++) {
        uint32_t off = st * (KV_STAGE_U32 * 4);
        int kb = st * 128;
#pragma unroll
        for (int j = 0; j < 4; j++) CP16(dA + off + j * 16, gA + kb + j * 16);
#pragma unroll
        for (int j = 0; j < 2; j++) CP16(dB + off + j * 16, gB + kb + j * 16);
        CP_COMMIT();
    }

    for (int ch = 0; ch < CHUNKS; ch++) {
        CP_WAIT1();
        __syncthreads();
        const uint32_t* sA = skv + (ch & 1) * KV_STAGE_U32;
        const uint32_t* sBp = sA + 128 * KV_STRIDE;

#pragma unroll
        for (int ks = 0; ks < 4; ks++) {
            int kk = ks * 8;
            uint32_t af[2][4];
#pragma unroll
            for (int mt = 0; mt < 2; mt++) {
                int r = warp_m * 32 + mt * 16 + lr;
                int c = kk + lc;
                af[mt][0] = sA[r * KV_STRIDE + c];
                af[mt][1] = sA[(r + 8) * KV_STRIDE + c];
                af[mt][2] = sA[r * KV_STRIDE + c + 4];
                af[mt][3] = sA[(r + 8) * KV_STRIDE + c + 4];
            }
            uint32_t bf[4][2];
#pragma unroll
            for (int nt = 0; nt < 4; nt++) {
                int n = warp_n * 32 + nt * 8 + lr;
                bf[nt][0] = sBp[n * KV_STRIDE + kk + lc];
                bf[nt][1] = sBp[n * KV_STRIDE + kk + lc + 4];
            }
#pragma unroll
            for (int mt = 0; mt < 2; mt++)
#pragma unroll
                for (int nt = 0; nt < 4; nt++)
                    MMA_BF16(acc[mt][nt], af[mt], bf[nt]);
        }
        __syncthreads();
        if (ch < CHUNKS - 2) {
            uint32_t off = (ch & 1) * (KV_STAGE_U32 * 4);
            int kb = (ch + 2) * 128;
#pragma unroll
            for (int j = 0; j < 4; j++) CP16(dA + off + j * 16, gA + kb + j * 16);
#pragma unroll
            for (int j = 0; j < 2; j++) CP16(dB + off + j * 16, gB + kb + j * 16);
        }
        CP_COMMIT();
    }

    // epilogue
#pragma unroll
    for (int mt = 0; mt < 2; mt++) {
        int r = m0 + warp_m * 32 + mt * 16 + lr;
#pragma unroll
        for (int nt = 0; nt < 4; nt++) {
            int cn = n0 + warp_n * 32 + nt * 8 + 2 * lc;
            float2 lo = make_float2(acc[mt][nt][0], acc[mt][nt][1]);
            float2 hi = make_float2(acc[mt][nt][2], acc[mt][nt][3]);
            if (EPI == 0) {          // k | v
                float* dst = (n0 < 384) ? p0 : p1;
                int c = (n0 < 384) ? cn : cn - 384;
                *(float2*)&dst[(size_t)r * HDH + c] = lo;
                *(float2*)&dst[(size_t)(r + 8) * HDH + c] = hi;
            } else if (EPI == 1) {   // q | gpre(+bg)
                if (n0 < 384) {
                    *(float2*)&p0[(size_t)r * HDH + cn] = lo;
                    *(float2*)&p0[(size_t)(r + 8) * HDH + cn] = hi;
                } else {
                    int c = cn - 384;
                    float2 bb = *(const float2*)&q0[c];
                    lo.x += bb.x; lo.y += bb.y; hi.x += bb.x; hi.y += bb.y;
                    *(float2*)&p1[(size_t)r * HDH + c] = lo;
                    *(float2*)&p1[(size_t)(r + 8) * HDH + c] = hi;
                }
            } else {                 // out = node + acc + bback
                float2 bb = *(const float2*)&q1[cn];
                float2 n1 = *(const float2*)&q0[(size_t)r * DIM + cn];
                float2 n2 = *(const float2*)&q0[(size_t)(r + 8) * DIM + cn];
                lo.x += bb.x + n1.x; lo.y += bb.y + n1.y;
                hi.x += bb.x + n2.x; hi.y += bb.y + n2.y;
                *(float2*)&p0[(size_t)r * DIM + cn] = lo;
                *(float2*)&p0[(size_t)(r + 8) * DIM + cn] = hi;
            }
        }
    }
}

// ---------------- kernel 3: attention (flash-style, cp.async 2-stage) --------
#define ATTN_SMEM_BYTES (25216 * 4)

__global__ void __launch_bounds__(256) attn_kernel(const int* __restrict__ mask)
{
    extern __shared__ float sm[];
    int*   sMaskAll = (int*)(sm + 24576);
    float* sML  = sm + 24704;
    float* cAcc = sm;

    int t = blockIdx.x >> 2;
    if (t >= g_numTiles) return;
    int hp = blockIdx.x & 3;
    int b = g_tile_b[t], n0 = g_tile_n0[t], nv = g_tile_nv[t];
    int tid = threadIdx.x, w = tid >> 5, lane = tid & 31;
    int hl = w & 1, st = w >> 1;
    int h = hp * 2 + hl;

    float qv[48];
    if (lane < nv) {
        const float4* qp = (const float4*)&g_q[(n0 + lane) * HDH + h * D_HEAD];
#pragma unroll
        for (int i = 0; i < 12; i++) {
            float4 v = qp[i];
            qv[4 * i] = v.x; qv[4 * i + 1] = v.y; qv[4 * i + 2] = v.z; qv[4 * i + 3] = v.w;
        }
    } else {
#pragma unroll
        for (int i = 0; i < 48; i++) qv[i] = 0.f;
    }

    float m = -1e30f, l = 0.f;
    float acc[48];
#pragma unroll
    for (int i = 0; i < 48; i++) acc[i] = 0.f;

    uint32_t sb = smem_u32(sm);
    const char* Kg = (const char*)g_k;
    const char* Vg = (const char*)g_v;

    uint32_t so16[6];
    long     gOff[6];
#pragma unroll
    for (int q8 = 0; q8 < 6; q8++) {
        int idx = tid + q8 * 256;
        int row = idx / 24, c4 = idx % 24;
        so16[q8] = (uint32_t)(row * 24 + c4) * 16;
        gOff[q8] = ((long)(b * S_LEN + row) * 96 + hp * 24 + c4) * 16;
    }
    const char* maskSrc = (const char*)(mask + (long)b * S_LEN + tid * 4);

#pragma unroll
    for (int cj = 0; cj < 2; cj++) {
        uint32_t kb = sb + (uint32_t)(cj * 12288) * 4;
        long chOff = (long)cj * 64 * 96 * 16;
#pragma unroll
        for (int q8 = 0; q8 < 6; q8++) {
            CP16(kb + so16[q8], Kg + gOff[q8] + chOff);
            CP16(kb + 6144 * 4 + so16[q8], Vg + gOff[q8] + chOff);
        }
        if (tid < 16)
            CP16(sb + (uint32_t)(24576 + cj * 64) * 4 + tid * 16,
                 maskSrc + (long)cj * 256);
        CP_COMMIT();
    }

    for (int ci = 0; ci < 16; ci++) {
        CP_WAIT1();
        __syncthreads();
        const float* sK = sm + (ci & 1) * 12288;
        const float* sV = sK + 6144;
        const int* sMask = sMaskAll + (ci & 1) * 64;

        float sc16[16];
#pragma unroll 4
        for (int i = 0; i < 16; i++) {
            int s = 4 * i + st;
            if (sMask[s]) {
                const float4* kr = (const float4*)&sK[s * 96 + hl * 48];
                float d0 = 0.f, d1 = 0.f, d2 = 0.f, d3 = 0.f;
#pragma unroll
                for (int i4 = 0; i4 < 12; i4++) {
                    float4 kk = kr[i4];
                    d0 = fmaf(qv[4 * i4 + 0], kk.x, d0);
                    d1 = fmaf(qv[4 * i4 + 1], kk.y, d1);
                    d2 = fmaf(qv[4 * i4 + 2], kk.z, d2);
                    d3 = fmaf(qv[4 * i4 + 3], kk.w, d3);
                }
                sc16[i] = ((d0 + d1) + (d2 + d3)) * INV_SCALE;
            } else {
                sc16[i] = -1e30f;
            }
        }
        float mc = -1e30f;
#pragma unroll
        for (int i = 0; i < 16; i++) mc = fmaxf(mc, sc16[i]);
        if (mc > -1e29f) {
            float mn = fmaxf(m, mc);
            float f = __expf(m - mn);
            l *= f;
#pragma unroll
            for (int d = 0; d < 48; d++) acc[d] *= f;
            m = mn;
#pragma unroll 2
            for (int i = 0; i < 16; i++) {
                if (sc16[i] > -1e29f) {
                    float p = __expf(sc16[i] - m);
                    l += p;
                    const float4* vr = (const float4*)&sV[(4 * i + st) * 96 + hl * 48];
#pragma unroll
                    for (int i4 = 0; i4 < 12; i4++) {
                        float4 vv = vr[i4];
                        acc[4 * i4 + 0] = fmaf(p, vv.x, acc[4 * i4 + 0]);
                        acc[4 * i4 + 1] = fmaf(p, vv.y, acc[4 * i4 + 1]);
                        acc[4 * i4 + 2] = fmaf(p, vv.z, acc[4 * i4 + 2]);
                        acc[4 * i4 + 3] = fmaf(p, vv.w, acc[4 * i4 + 3]);
                    }
                }
            }
        }
        __syncthreads();
        if (ci < 14) {
            int cj = ci + 2;
            uint32_t kb = sb + (uint32_t)((cj & 1) * 12288) * 4;
            long chOff = (long)cj * 64 * 96 * 16;
#pragma unroll
            for (int q8 = 0; q8 < 6; q8++) {
                CP16(kb + so16[q8], Kg + gOff[q8] + chOff);
                CP16(kb + 6144 * 4 + so16[q8], Vg + gOff[q8] + chOff);
            }
            if (tid < 16)
                CP16(sb + (uint32_t)(24576 + (cj & 1) * 64) * 4 + tid * 16,
                     maskSrc + (long)cj * 256);
        }
        CP_COMMIT();
    }
    CP_WAIT0();
    __syncthreads();

    {
        int r = (st * 32 + lane) * 2 + hl;
        sML[r * 2 + 0] = m;
        sML[r * 2 + 1] = l;
#pragma unroll
        for (int d = 0; d < 48; d++) cAcc[r * 48 + d] = acc[d];
    }
    __syncthreads();

    if (tid < 64) {
        int j = tid >> 1, hlf = tid & 1;
        int hf = hp * 2 + hlf;
        float M = -1e30f;
#pragma unroll
        for (int s = 0; s < 4; s++)
            M = fmaxf(M, sML[((s * 32 + j) * 2 + hlf) * 2]);
        float L = 0.f, e[4];
#pragma unroll
        for (int s = 0; s < 4; s++) {
            float ms = sML[((s * 32 + j) * 2 + hlf) * 2];
            float ls = sML[((s * 32 + j) * 2 + hlf) * 2 + 1];
            e[s] = __expf(ms - M);
            L += ls * e[s];
        }
        float invL = 1.f / (L + 1e-9f);
        if (j < nv) {
            float* outp = &g_feat[(n0 + j) * HDH + hf * D_HEAD];
            for (int d = 0; d < 48; d++) {
                float F = 0.f;
#pragma unroll
                for (int s = 0; s < 4; s++)
                    F += cAcc[((s * 32 + j) * 2 + hlf) * 48 + d] * e[s];
                outp[d] = F * invL;
            }
        }
    }
}

// ---------------- launch -----------------------------------------------------
extern "C" void kernel_launch(void* const* d_in, const int* in_sizes, int n_in,
                              void* d_out, int out_size) {
    const float* node  = (const float*)d_in[0];
    const float* emb   = (const float*)d_in[1];
    const int*   mask  = (const int*)d_in[2];
    const void*  batch = d_in[3];
    const float* ln_g  = (const float*)d_in[4];
    const float* ln_b  = (const float*)d_in[5];
    const float* Wq    = (const float*)d_in[6];
    const float* Wk    = (const float*)d_in[7];
    const float* Wv    = (const float*)d_in[8];
    const float* Wg    = (const float*)d_in[9];
    const float* bg    = (const float*)d_in[10];
    const float* Wback = (const float*)d_in[11];
    const float* bback = (const float*)d_in[12];
    float* out = (float*)d_out;

    float *p_q, *p_gpre, *p_k, *p_v;
    bf16 *p_y, *p_gf, *p_wt, *p_wqg, *p_wbt, *p_embt;
    cudaGetSymbolAddress((void**)&p_q,    g_q);
    cudaGetSymbolAddress((void**)&p_gpre, g_gpre);
    cudaGetSymbolAddress((void**)&p_k,    g_k);
    cudaGetSymbolAddress((void**)&p_v,    g_v);
    cudaGetSymbolAddress((void**)&p_y,    g_y);
    cudaGetSymbolAddress((void**)&p_gf,   g_gf);
    cudaGetSymbolAddress((void**)&p_wt,   g_wt);
    cudaGetSymbolAddress((void**)&p_wqg,  g_wqg);
    cudaGetSymbolAddress((void**)&p_wbt,  g_wbt);
    cudaGetSymbolAddress((void**)&p_embt, g_embt);

    cudaFuncSetAttribute(attn_kernel,
                         cudaFuncAttributeMaxDynamicSharedMemorySize, ATTN_SMEM_BYTES);
    cudaFuncSetAttribute(gemm_bf16<4, 1>,
                         cudaFuncAttributeMaxDynamicSharedMemorySize, KV_SMEM_BYTES);
    cudaFuncSetAttribute(gemm_bf16<20, 0>,
                         cudaFuncAttributeMaxDynamicSharedMemorySize, KV_SMEM_BYTES);
    cudaFuncSetAttribute(gemm_bf16<6, 2>,
                         cudaFuncAttributeMaxDynamicSharedMemorySize, KV_SMEM_BYTES);

    setup_kernel<<<1, 256>>>(batch);
    cvt_kernel<<<8192 * D_SEQ / (8 * 256), 256>>>(emb);
    // B-operand transposes (bf16, [n][k] layout)
    transpose_bf16<<<dim3(DIM / 32, HDH / 32), 256>>>(Wq, DIM, HDH, p_wqg, 0);
    transpose_bf16<<<dim3(DIM / 32, HDH / 32), 256>>>(Wg, DIM, HDH, p_wqg, 384);
    transpose_bf16<<<dim3(D_SEQ / 32, HDH / 32), 256>>>(Wk, D_SEQ, HDH, p_wt, 0);
    transpose_bf16<<<dim3(D_SEQ / 32, HDH / 32), 256>>>(Wv, D_SEQ, HDH, p_wt, 384);
    transpose_bf16<<<dim3(HDH / 32, DIM / 32), 256>>>(Wback, HDH, DIM, p_wbt, 0);
    ln_kernel<<<N_NODE / 8, 256>>>(node, ln_g, ln_b);
    // GEMM1: [q|gpre] = y @ [Wq|Wg]  (+bg on gpre half)
    gemm_bf16<4, 1><<<dim3(16, 12), 256, KV_SMEM_BYTES>>>(
        p_y, p_wqg, p_q, p_gpre, bg, nullptr);
    // GEMM2: [k|v] = embt @ [Wk|Wv]
    gemm_bf16<20, 0><<<dim3(64, 12), 256, KV_SMEM_BYTES>>>(
        p_embt, p_wt, p_k, p_v, nullptr, nullptr);
    attn_kernel<<<288, 256, ATTN_SMEM_BYTES>>>(mask);
    gf_kernel<<<N_NODE * HDH / (8 * 256), 256>>>();
    // GEMM3: out = node + (gate*feat) @ Wback + bback
    gemm_bf16<6, 2><<<dim3(16, 4), 256, KV_SMEM_BYTES>>>(
        p_gf, p_wbt, out, nullptr, node, bback);
}